// round 9
// baseline (speedup 1.0000x reference)
#include <cuda_runtime.h>
#include <cstdint>
#include <cstddef>

#define N_NODES 20000
#define N_EDGES 200000
#define HID 128
#define NH 8
#define LAYERS 7
#define MLP_K 288      // padded K (285 -> 288)
#define MLP_LD 320     // padded row stride / N

// ---------------- scratch (static device globals) ----------------
__device__ float g_h[N_NODES * HID];
__device__ float g_x[N_NODES * HID];
__device__ float g_qkv[N_NODES * 384];
__device__ float g_attn[N_NODES * HID];
__device__ float g_tmp[N_NODES * HID];
__device__ float g_y0[(size_t)N_EDGES * MLP_LD];
__device__ float g_y1[(size_t)N_EDGES * MLP_LD];
__device__ float g_Wpad[3 * MLP_K * MLP_LD];
__device__ float g_bpad[3 * MLP_LD];
__device__ float g_Wopad[MLP_LD * 2];
__device__ float g_Wqkv[LAYERS * HID * 384];
__device__ float g_bqkv[LAYERS * 384];
__device__ float g_ns[(size_t)N_NODES * MLP_LD];
__device__ float g_nd[(size_t)N_NODES * MLP_LD];
__device__ float g_tpc[15 * MLP_LD];
__device__ float g_trc[15 * MLP_LD];
__device__ float g_tpf[7 * MLP_LD];
__device__ float g_zero[MLP_LD];
__device__ int   g_deg[N_NODES];
__device__ int   g_rowptr[N_NODES + 1];
__device__ int   g_cursor[N_NODES];
__device__ int   g_srcs[N_EDGES];

__device__ __forceinline__ float tf32r(float x) {
    unsigned u;
    asm("cvt.rna.tf32.f32 %0, %1;" : "=r"(u) : "f"(x));
    return __uint_as_float(u);
}

// ---------------- embedding ----------------
__global__ void embed_kernel(const float* __restrict__ nf, const float* __restrict__ We,
                             const float* __restrict__ be, float* __restrict__ h) {
    int idx = blockIdx.x * blockDim.x + threadIdx.x;
    if (idx >= N_NODES * HID) return;
    int n = idx >> 7, c = idx & 127;
    h[idx] = fmaf(nf[n * 2 + 0], We[c], fmaf(nf[n * 2 + 1], We[HID + c], be[c]));
}

// ---------------- LayerNorm: warp per node ----------------
__global__ void ln_kernel(const float* __restrict__ h, const float* __restrict__ g,
                          const float* __restrict__ b, float* __restrict__ x) {
    int node = (blockIdx.x * blockDim.x + threadIdx.x) >> 5;
    int lane = threadIdx.x & 31;
    if (node >= N_NODES) return;
    float4 v = *(const float4*)&h[node * HID + lane * 4];
    float s = v.x + v.y + v.z + v.w;
    #pragma unroll
    for (int o = 16; o; o >>= 1) s += __shfl_xor_sync(0xffffffffu, s, o);
    float mu = s * (1.0f / 128.0f);
    float dx = v.x - mu, dy = v.y - mu, dz = v.z - mu, dw = v.w - mu;
    float q = dx * dx + dy * dy + dz * dz + dw * dw;
    #pragma unroll
    for (int o = 16; o; o >>= 1) q += __shfl_xor_sync(0xffffffffu, q, o);
    float rs = rsqrtf(q * (1.0f / 128.0f) + 1e-5f);
    float4 gv = *(const float4*)&g[lane * 4];
    float4 bv = *(const float4*)&b[lane * 4];
    float4 o4;
    o4.x = fmaf(dx * rs, gv.x, bv.x);
    o4.y = fmaf(dy * rs, gv.y, bv.y);
    o4.z = fmaf(dz * rs, gv.z, bv.z);
    o4.w = fmaf(dw * rs, gv.w, bv.w);
    *(float4*)&x[node * HID + lane * 4] = o4;
}

// ---------------- 3xTF32 tensor-core GEMM (node pipeline, fp32-equivalent) ----------
// C[M,N] = act(A[M,K] @ W[K,N] + bias [+ res]); K % 16 == 0, N % 4 == 0.
// 256 threads, 8 warps (2M x 4N), block tile 128x128, warp tile 64x32.
__global__ __launch_bounds__(256)
void mma3b_gemm_kernel(const float* __restrict__ A, const float* __restrict__ W,
                       const float* __restrict__ bias, const float* __restrict__ res,
                       float* __restrict__ C, int M, int K, int N, int relu) {
    __shared__ float Ah[128][20], Al[128][20];
    __shared__ float Bh[16][136], Bl[16][136];   // 136 % 32 == 8 -> conflict-free frags

    int tid = threadIdx.x;
    int lane = tid & 31, warp = tid >> 5;
    int warpM = warp & 1, warpN = warp >> 1;     // 2 x 4
    int rowBase = blockIdx.y * 128;
    int colBase = blockIdx.x * 128;
    int gq = lane >> 2, tg = lane & 3;

    float acc[4][4][4];
    #pragma unroll
    for (int mi = 0; mi < 4; mi++)
        #pragma unroll
        for (int ni = 0; ni < 4; ni++)
            #pragma unroll
            for (int r = 0; r < 4; r++) acc[mi][ni][r] = 0.0f;

    float4 ra[2], rb[2];

    auto loadG = [&](int k0) {
        #pragma unroll
        for (int it = 0; it < 2; it++) {
            int idx = tid + it * 256;
            int r = idx >> 2, c4 = (idx & 3) * 4;
            int gr = rowBase + r;
            ra[it] = (gr < M) ? *(const float4*)&A[(size_t)gr * K + k0 + c4]
                              : make_float4(0.f, 0.f, 0.f, 0.f);
        }
        #pragma unroll
        for (int it = 0; it < 2; it++) {
            int idx = tid + it * 256;
            int r = idx >> 5, c4 = (idx & 31) * 4;
            int gc = colBase + c4;
            rb[it] = (gc < N) ? *(const float4*)&W[(size_t)(k0 + r) * N + gc]
                              : make_float4(0.f, 0.f, 0.f, 0.f);
        }
    };
    auto storeS = [&]() {
        #pragma unroll
        for (int it = 0; it < 2; it++) {
            int idx = tid + it * 256;
            int r = idx >> 2, c4 = (idx & 3) * 4;
            float vals[4] = {ra[it].x, ra[it].y, ra[it].z, ra[it].w};
            #pragma unroll
            for (int j = 0; j < 4; j++) {
                float hi = tf32r(vals[j]);
                Ah[r][c4 + j] = hi;
                Al[r][c4 + j] = tf32r(vals[j] - hi);
            }
        }
        #pragma unroll
        for (int it = 0; it < 2; it++) {
            int idx = tid + it * 256;
            int r = idx >> 5, c4 = (idx & 31) * 4;
            float vals[4] = {rb[it].x, rb[it].y, rb[it].z, rb[it].w};
            #pragma unroll
            for (int j = 0; j < 4; j++) {
                float hi = tf32r(vals[j]);
                Bh[r][c4 + j] = hi;
                Bl[r][c4 + j] = tf32r(vals[j] - hi);
            }
        }
    };

    loadG(0);
    storeS();
    __syncthreads();

    int nchunk = K >> 4;
    #pragma unroll 1
    for (int c = 0; c < nchunk; c++) {
        if (c + 1 < nchunk) loadG((c + 1) << 4);

        #pragma unroll
        for (int kk = 0; kk < 16; kk += 8) {
            unsigned ah[4][4], al[4][4];
            #pragma unroll
            for (int mi = 0; mi < 4; mi++) {
                int r = warpM * 64 + mi * 16 + gq;
                int cc = kk + tg;
                ah[mi][0] = __float_as_uint(Ah[r][cc]);
                ah[mi][1] = __float_as_uint(Ah[r + 8][cc]);
                ah[mi][2] = __float_as_uint(Ah[r][cc + 4]);
                ah[mi][3] = __float_as_uint(Ah[r + 8][cc + 4]);
                al[mi][0] = __float_as_uint(Al[r][cc]);
                al[mi][1] = __float_as_uint(Al[r + 8][cc]);
                al[mi][2] = __float_as_uint(Al[r][cc + 4]);
                al[mi][3] = __float_as_uint(Al[r + 8][cc + 4]);
            }
            #pragma unroll
            for (int ni = 0; ni < 4; ni++) {
                int bc = warpN * 32 + ni * 8 + gq;
                unsigned bh0 = __float_as_uint(Bh[kk + tg][bc]);
                unsigned bh1 = __float_as_uint(Bh[kk + tg + 4][bc]);
                unsigned bl0 = __float_as_uint(Bl[kk + tg][bc]);
                unsigned bl1 = __float_as_uint(Bl[kk + tg + 4][bc]);
                #pragma unroll
                for (int mi = 0; mi < 4; mi++) {
                    asm volatile(
                        "mma.sync.aligned.m16n8k8.row.col.f32.tf32.tf32.f32 "
                        "{%0,%1,%2,%3},{%4,%5,%6,%7},{%8,%9},{%0,%1,%2,%3};"
                        : "+f"(acc[mi][ni][0]), "+f"(acc[mi][ni][1]),
                          "+f"(acc[mi][ni][2]), "+f"(acc[mi][ni][3])
                        : "r"(ah[mi][0]), "r"(ah[mi][1]), "r"(ah[mi][2]), "r"(ah[mi][3]),
                          "r"(bh0), "r"(bh1));
                    asm volatile(
                        "mma.sync.aligned.m16n8k8.row.col.f32.tf32.tf32.f32 "
                        "{%0,%1,%2,%3},{%4,%5,%6,%7},{%8,%9},{%0,%1,%2,%3};"
                        : "+f"(acc[mi][ni][0]), "+f"(acc[mi][ni][1]),
                          "+f"(acc[mi][ni][2]), "+f"(acc[mi][ni][3])
                        : "r"(al[mi][0]), "r"(al[mi][1]), "r"(al[mi][2]), "r"(al[mi][3]),
                          "r"(bh0), "r"(bh1));
                    asm volatile(
                        "mma.sync.aligned.m16n8k8.row.col.f32.tf32.tf32.f32 "
                        "{%0,%1,%2,%3},{%4,%5,%6,%7},{%8,%9},{%0,%1,%2,%3};"
                        : "+f"(acc[mi][ni][0]), "+f"(acc[mi][ni][1]),
                          "+f"(acc[mi][ni][2]), "+f"(acc[mi][ni][3])
                        : "r"(ah[mi][0]), "r"(ah[mi][1]), "r"(ah[mi][2]), "r"(ah[mi][3]),
                          "r"(bl0), "r"(bl1));
                }
            }
        }
        __syncthreads();
        if (c + 1 < nchunk) {
            storeS();
            __syncthreads();
        }
    }

    // epilogue: bias [+res] [+relu], guarded for N not multiple of 128
    #pragma unroll
    for (int ni = 0; ni < 4; ni++) {
        int gc = colBase + warpN * 32 + ni * 8 + 2 * tg;
        if (gc >= N) continue;
        float2 bv = *(const float2*)&bias[gc];
        #pragma unroll
        for (int mi = 0; mi < 4; mi++) {
            int r0 = rowBase + warpM * 64 + mi * 16 + gq;
            if (r0 < M) {
                float2 o;
                o.x = acc[mi][ni][0] + bv.x;
                o.y = acc[mi][ni][1] + bv.y;
                if (res) {
                    float2 rv = *(const float2*)&res[(size_t)r0 * N + gc];
                    o.x += rv.x; o.y += rv.y;
                }
                if (relu) { o.x = fmaxf(o.x, 0.f); o.y = fmaxf(o.y, 0.f); }
                *(float2*)&C[(size_t)r0 * N + gc] = o;
            }
            int r1 = r0 + 8;
            if (r1 < M) {
                float2 o;
                o.x = acc[mi][ni][2] + bv.x;
                o.y = acc[mi][ni][3] + bv.y;
                if (res) {
                    float2 rv = *(const float2*)&res[(size_t)r1 * N + gc];
                    o.x += rv.x; o.y += rv.y;
                }
                if (relu) { o.x = fmaxf(o.x, 0.f); o.y = fmaxf(o.y, 0.f); }
                *(float2*)&C[(size_t)r1 * N + gc] = o;
            }
        }
    }
}

// ---------------- tf32 tensor-core GEMM (MLP layers 2,3) ----------------
// When WoT != nullptr: fused output projection — no C store; instead
// out[r,0:2] += relu(acc+bias) @ WoT (atomicAdd; out pre-initialized with bo).
#define GK 288
#define GN 320
#define MBN 160
#define ASTRIDE 20
#define BSTRIDE 168

__global__ __launch_bounds__(256)
void mma_gemm_kernel(const float* __restrict__ A, const float* __restrict__ W,
                     const float* __restrict__ bias, float* __restrict__ C, int M,
                     const float* __restrict__ WoT, float* __restrict__ out) {
    __shared__ float As[2][128][ASTRIDE];
    __shared__ float Bs[2][16][BSTRIDE];

    int tid = threadIdx.x;
    int lane = tid & 31, warp = tid >> 5;
    int warpM = warp & 1, warpN = warp >> 1;     // 2 x 4
    int rowBase = blockIdx.y * 128;
    int colBase = blockIdx.x * MBN;
    int gq = lane >> 2, tg = lane & 3;

    float acc[4][5][4];
    #pragma unroll
    for (int mi = 0; mi < 4; mi++)
        #pragma unroll
        for (int ni = 0; ni < 5; ni++)
            #pragma unroll
            for (int r = 0; r < 4; r++) acc[mi][ni][r] = 0.0f;

    int ar[2], ac[2];
    bool av[2];
    #pragma unroll
    for (int it = 0; it < 2; it++) {
        int idx = tid + it * 256;
        ar[it] = idx >> 2; ac[it] = (idx & 3) * 4;
        av[it] = (rowBase + ar[it]) < M;
    }
    int br[3], bc4[3];
    bool bvld[3];
    #pragma unroll
    for (int it = 0; it < 3; it++) {
        int idx = tid + it * 256;
        bvld[it] = idx < 640;
        br[it] = idx / 40; bc4[it] = (idx % 40) * 4;
    }

    float4 ra[2], rb[3];
    #pragma unroll
    for (int it = 0; it < 2; it++)
        ra[it] = av[it] ? *(const float4*)&A[(size_t)(rowBase + ar[it]) * GN + ac[it]]
                        : make_float4(0.f, 0.f, 0.f, 0.f);
    #pragma unroll
    for (int it = 0; it < 3; it++)
        rb[it] = bvld[it] ? *(const float4*)&W[(size_t)br[it] * GN + colBase + bc4[it]]
                          : make_float4(0.f, 0.f, 0.f, 0.f);

    #pragma unroll
    for (int it = 0; it < 2; it++) {
        As[0][ar[it]][ac[it] + 0] = tf32r(ra[it].x);
        As[0][ar[it]][ac[it] + 1] = tf32r(ra[it].y);
        As[0][ar[it]][ac[it] + 2] = tf32r(ra[it].z);
        As[0][ar[it]][ac[it] + 3] = tf32r(ra[it].w);
    }
    #pragma unroll
    for (int it = 0; it < 3; it++) {
        if (!bvld[it]) continue;
        Bs[0][br[it]][bc4[it] + 0] = tf32r(rb[it].x);
        Bs[0][br[it]][bc4[it] + 1] = tf32r(rb[it].y);
        Bs[0][br[it]][bc4[it] + 2] = tf32r(rb[it].z);
        Bs[0][br[it]][bc4[it] + 3] = tf32r(rb[it].w);
    }
    __syncthreads();

    const int NCHUNK = GK / 16;   // 18
    #pragma unroll 1
    for (int c = 0; c < NCHUNK; c++) {
        int cur = c & 1;
        if (c < NCHUNK - 1) {
            int k0 = (c + 1) * 16;
            #pragma unroll
            for (int it = 0; it < 2; it++)
                ra[it] = av[it]
                    ? *(const float4*)&A[(size_t)(rowBase + ar[it]) * GN + k0 + ac[it]]
                    : make_float4(0.f, 0.f, 0.f, 0.f);
            #pragma unroll
            for (int it = 0; it < 3; it++)
                rb[it] = bvld[it]
                    ? *(const float4*)&W[(size_t)(k0 + br[it]) * GN + colBase + bc4[it]]
                    : make_float4(0.f, 0.f, 0.f, 0.f);
        }

        #pragma unroll
        for (int kk = 0; kk < 16; kk += 8) {
            unsigned af[4][4];
            #pragma unroll
            for (int mi = 0; mi < 4; mi++) {
                int r = warpM * 64 + mi * 16 + gq;
                int cc = kk + tg;
                af[mi][0] = __float_as_uint(As[cur][r][cc]);
                af[mi][1] = __float_as_uint(As[cur][r + 8][cc]);
                af[mi][2] = __float_as_uint(As[cur][r][cc + 4]);
                af[mi][3] = __float_as_uint(As[cur][r + 8][cc + 4]);
            }
            #pragma unroll
            for (int ni = 0; ni < 5; ni++) {
                int bc = warpN * 40 + ni * 8 + gq;
                unsigned b0 = __float_as_uint(Bs[cur][kk + tg][bc]);
                unsigned b1 = __float_as_uint(Bs[cur][kk + tg + 4][bc]);
                #pragma unroll
                for (int mi = 0; mi < 4; mi++) {
                    asm volatile(
                        "mma.sync.aligned.m16n8k8.row.col.f32.tf32.tf32.f32 "
                        "{%0,%1,%2,%3},{%4,%5,%6,%7},{%8,%9},{%0,%1,%2,%3};"
                        : "+f"(acc[mi][ni][0]), "+f"(acc[mi][ni][1]),
                          "+f"(acc[mi][ni][2]), "+f"(acc[mi][ni][3])
                        : "r"(af[mi][0]), "r"(af[mi][1]), "r"(af[mi][2]), "r"(af[mi][3]),
                          "r"(b0), "r"(b1));
                }
            }
        }

        if (c < NCHUNK - 1) {
            int nxt = cur ^ 1;
            #pragma unroll
            for (int it = 0; it < 2; it++) {
                As[nxt][ar[it]][ac[it] + 0] = tf32r(ra[it].x);
                As[nxt][ar[it]][ac[it] + 1] = tf32r(ra[it].y);
                As[nxt][ar[it]][ac[it] + 2] = tf32r(ra[it].z);
                As[nxt][ar[it]][ac[it] + 3] = tf32r(ra[it].w);
            }
            #pragma unroll
            for (int it = 0; it < 3; it++) {
                if (!bvld[it]) continue;
                Bs[nxt][br[it]][bc4[it] + 0] = tf32r(rb[it].x);
                Bs[nxt][br[it]][bc4[it] + 1] = tf32r(rb[it].y);
                Bs[nxt][br[it]][bc4[it] + 2] = tf32r(rb[it].z);
                Bs[nxt][br[it]][bc4[it] + 3] = tf32r(rb[it].w);
            }
            __syncthreads();
        }
    }

    if (WoT == nullptr) {
        // normal epilogue: relu(acc + bias) -> C
        #pragma unroll
        for (int ni = 0; ni < 5; ni++) {
            int gc = colBase + warpN * 40 + ni * 8 + 2 * tg;
            float2 bv = *(const float2*)&bias[gc];
            #pragma unroll
            for (int mi = 0; mi < 4; mi++) {
                int r0 = rowBase + warpM * 64 + mi * 16 + gq;
                if (r0 < M) {
                    float2 o;
                    o.x = fmaxf(acc[mi][ni][0] + bv.x, 0.f);
                    o.y = fmaxf(acc[mi][ni][1] + bv.y, 0.f);
                    *(float2*)&C[(size_t)r0 * GN + gc] = o;
                }
                int r1 = r0 + 8;
                if (r1 < M) {
                    float2 o;
                    o.x = fmaxf(acc[mi][ni][2] + bv.x, 0.f);
                    o.y = fmaxf(acc[mi][ni][3] + bv.y, 0.f);
                    *(float2*)&C[(size_t)r1 * GN + gc] = o;
                }
            }
        }
    } else {
        // fused epilogue: out[r] += relu(acc+bias) @ WoT  (this block's 160 cols)
        float p[4][2][2];
        #pragma unroll
        for (int mi = 0; mi < 4; mi++) {
            p[mi][0][0] = 0.f; p[mi][0][1] = 0.f;
            p[mi][1][0] = 0.f; p[mi][1][1] = 0.f;
        }
        #pragma unroll
        for (int ni = 0; ni < 5; ni++) {
            int gc = colBase + warpN * 40 + ni * 8 + 2 * tg;
            float2 bv = *(const float2*)&bias[gc];
            float w00 = WoT[gc * 2 + 0],       w01 = WoT[gc * 2 + 1];
            float w10 = WoT[(gc + 1) * 2 + 0], w11 = WoT[(gc + 1) * 2 + 1];
            #pragma unroll
            for (int mi = 0; mi < 4; mi++) {
                float ox = fmaxf(acc[mi][ni][0] + bv.x, 0.f);
                float oy = fmaxf(acc[mi][ni][1] + bv.y, 0.f);
                p[mi][0][0] = fmaf(ox, w00, fmaf(oy, w10, p[mi][0][0]));
                p[mi][0][1] = fmaf(ox, w01, fmaf(oy, w11, p[mi][0][1]));
                float zx = fmaxf(acc[mi][ni][2] + bv.x, 0.f);
                float zy = fmaxf(acc[mi][ni][3] + bv.y, 0.f);
                p[mi][1][0] = fmaf(zx, w00, fmaf(zy, w10, p[mi][1][0]));
                p[mi][1][1] = fmaf(zx, w01, fmaf(zy, w11, p[mi][1][1]));
            }
        }
        // reduce over tg (lane bits 0-1), then atomicAdd from tg==0 lanes
        #pragma unroll
        for (int mi = 0; mi < 4; mi++) {
            #pragma unroll
            for (int hf = 0; hf < 2; hf++) {
                float v0 = p[mi][hf][0], v1 = p[mi][hf][1];
                v0 += __shfl_xor_sync(0xffffffffu, v0, 1);
                v0 += __shfl_xor_sync(0xffffffffu, v0, 2);
                v1 += __shfl_xor_sync(0xffffffffu, v1, 1);
                v1 += __shfl_xor_sync(0xffffffffu, v1, 2);
                if (tg == 0) {
                    int r = rowBase + warpM * 64 + mi * 16 + gq + hf * 8;
                    if (r < M) {
                        atomicAdd(&out[(size_t)r * 2 + 0], v0);
                        atomicAdd(&out[(size_t)r * 2 + 1], v1);
                    }
                }
            }
        }
    }
}

// ---------------- CSR build ----------------
__global__ void deg_zero_kernel(int* __restrict__ deg) {
    int i = blockIdx.x * blockDim.x + threadIdx.x;
    if (i < N_NODES) deg[i] = 0;
}
__global__ void deg_count_kernel(const int* __restrict__ dst, int* __restrict__ deg) {
    int e = blockIdx.x * blockDim.x + threadIdx.x;
    if (e < N_EDGES) atomicAdd(&deg[dst[e]], 1);
}
__global__ void scan_kernel(const int* __restrict__ deg, int* __restrict__ rowptr) {
    __shared__ int sums[1024];
    const int CH = (N_NODES + 1023) / 1024;   // 20
    int t = threadIdx.x;
    int base = t * CH;
    int local[CH];
    int s = 0;
    #pragma unroll
    for (int i = 0; i < CH; i++) {
        int idx = base + i;
        local[i] = (idx < N_NODES) ? deg[idx] : 0;
        s += local[i];
    }
    sums[t] = s;
    __syncthreads();
    for (int off = 1; off < 1024; off <<= 1) {
        int v = (t >= off) ? sums[t - off] : 0;
        __syncthreads();
        sums[t] += v;
        __syncthreads();
    }
    int run = sums[t] - s;
    #pragma unroll
    for (int i = 0; i < CH; i++) {
        int idx = base + i;
        if (idx < N_NODES) rowptr[idx] = run;
        run += local[i];
    }
    if (t == 1023) rowptr[N_NODES] = sums[1023];
}
__global__ void cursor_kernel(const int* __restrict__ rowptr, int* __restrict__ cur) {
    int i = blockIdx.x * blockDim.x + threadIdx.x;
    if (i < N_NODES) cur[i] = rowptr[i];
}
__global__ void scatter_kernel(const int* __restrict__ src, const int* __restrict__ dst,
                               int* __restrict__ cur, int* __restrict__ srcs) {
    int e = blockIdx.x * blockDim.x + threadIdx.x;
    if (e >= N_EDGES) return;
    int pos = atomicAdd(&cur[dst[e]], 1);
    srcs[pos] = src[e];
}

// ---------------- fused attention: warp per dst node, online softmax ----------------
__global__ void attn_kernel(const float* __restrict__ qkv, const int* __restrict__ rowptr,
                            const int* __restrict__ srcs, float* __restrict__ attn) {
    int d = (blockIdx.x * blockDim.x + threadIdx.x) >> 5;
    int lane = threadIdx.x & 31;
    if (d >= N_NODES) return;
    int beg = rowptr[d], end = rowptr[d + 1];
    if (beg == end) {
        *(float4*)&attn[(size_t)d * HID + lane * 4] = make_float4(0.f, 0.f, 0.f, 0.f);
        return;
    }
    float4 qv = *(const float4*)&qkv[(size_t)d * 384 + lane * 4];
    float m = -3.4e38f, den = 0.f;
    float4 acc = make_float4(0.f, 0.f, 0.f, 0.f);
    for (int j = beg; j < end; j++) {
        int s = srcs[j];
        float4 kv = *(const float4*)&qkv[(size_t)s * 384 + 128 + lane * 4];
        float4 vv = *(const float4*)&qkv[(size_t)s * 384 + 256 + lane * 4];
        float p = qv.x * kv.x + qv.y * kv.y + qv.z * kv.z + qv.w * kv.w;
        p += __shfl_xor_sync(0xffffffffu, p, 1);
        p += __shfl_xor_sync(0xffffffffu, p, 2);
        float sc = p * 0.25f;
        float nm = fmaxf(m, sc);
        float scale = __expf(m - nm);
        float ex = __expf(sc - nm);
        acc.x = acc.x * scale + ex * vv.x;
        acc.y = acc.y * scale + ex * vv.y;
        acc.z = acc.z * scale + ex * vv.z;
        acc.w = acc.w * scale + ex * vv.w;
        den = den * scale + ex;
        m = nm;
    }
    float inv = 1.0f / den;
    float4 o = make_float4(acc.x * inv, acc.y * inv, acc.z * inv, acc.w * inv);
    *(float4*)&attn[(size_t)d * HID + lane * 4] = o;
}

// ---------------- weight prep ----------------
__global__ void padW_kernel(const float* __restrict__ Wh, float* __restrict__ Wpad) {
    int idx = blockIdx.x * blockDim.x + threadIdx.x;
    if (idx >= 3 * MLP_K * MLP_LD) return;
    int i = idx / (MLP_K * MLP_LD);
    int rem = idx - i * (MLP_K * MLP_LD);
    int r = rem / MLP_LD, c = rem - r * MLP_LD;
    Wpad[idx] = (r < 285 && c < 285) ? Wh[i * 285 * 285 + r * 285 + c] : 0.0f;
}

__global__ void padb_kernel(const float* __restrict__ bh, float* __restrict__ bpad,
                            const float* __restrict__ Wo, float* __restrict__ Wopad,
                            float* __restrict__ zero) {
    int idx = blockIdx.x * blockDim.x + threadIdx.x;
    if (idx < 3 * MLP_LD) {
        int i = idx / MLP_LD, c = idx - i * MLP_LD;
        bpad[idx] = (c < 285) ? bh[i * 285 + c] : 0.0f;
    }
    if (idx < MLP_LD * 2) {
        int r = idx >> 1;
        Wopad[idx] = (r < 285) ? Wo[idx] : 0.0f;
    }
    if (idx < MLP_LD) zero[idx] = 0.0f;
}

__global__ void packqkv_kernel(const float* __restrict__ WQ, const float* __restrict__ WK,
                               const float* __restrict__ WV, const float* __restrict__ bQ,
                               const float* __restrict__ bK, const float* __restrict__ bV,
                               float* __restrict__ Wqkv, float* __restrict__ bqkv) {
    int idx = blockIdx.x * blockDim.x + threadIdx.x;
    if (idx < LAYERS * HID * 384) {
        int l = idx / (HID * 384);
        int rem = idx - l * (HID * 384);
        int r = rem / 384, c = rem - r * 384;
        float v;
        if (c < 128)      v = WQ[l * HID * HID + r * HID + c];
        else if (c < 256) v = WK[l * HID * HID + r * HID + (c - 128)];
        else              v = WV[l * HID * HID + r * HID + (c - 256)];
        Wqkv[idx] = v;
    }
    if (idx < LAYERS * 384) {
        int l = idx / 384, c = idx - l * 384;
        float v;
        if (c < 128)      v = bQ[l * HID + c];
        else if (c < 256) v = bK[l * HID + (c - 128)];
        else              v = bV[l * HID + (c - 256)];
        bqkv[idx] = v;
    }
}

__global__ void tables_kernel(const float* __restrict__ ce, const float* __restrict__ pe,
                              const float* __restrict__ W0, float* __restrict__ tpc,
                              float* __restrict__ trc, float* __restrict__ tpf) {
    int idx = blockIdx.x * blockDim.x + threadIdx.x;
    if (idx >= 37 * MLP_LD) return;
    int i = idx / MLP_LD, c = idx - i * MLP_LD;
    if (i < 15) {
        float s = 0.f;
        #pragma unroll
        for (int k = 0; k < 8; k++) s = fmaf(ce[i * 8 + k], W0[(256 + k) * MLP_LD + c], s);
        tpc[i * MLP_LD + c] = s;
    } else if (i < 30) {
        int ii = i - 15;
        float s = 0.f;
        #pragma unroll
        for (int k = 0; k < 8; k++) s = fmaf(ce[ii * 8 + k], W0[(264 + k) * MLP_LD + c], s);
        trc[ii * MLP_LD + c] = s;
    } else {
        int ii = i - 30;
        float s = 0.f;
        #pragma unroll
        for (int k = 0; k < 8; k++) s = fmaf(pe[ii * 8 + k], W0[(272 + k) * MLP_LD + c], s);
        tpf[ii * MLP_LD + c] = s;
    }
}

// ---------------- MLP layer-1 assemble: warp per edge ----------------
__global__ void assemble_kernel(const float* __restrict__ ns, const float* __restrict__ nd,
                                const float* __restrict__ tpc, const float* __restrict__ trc,
                                const float* __restrict__ tpf, const float* __restrict__ W0,
                                const float* __restrict__ num, const int* __restrict__ src,
                                const int* __restrict__ dst, const int* __restrict__ pc,
                                const int* __restrict__ rc, const int* __restrict__ pf,
                                float* __restrict__ y) {
    int e = (blockIdx.x * blockDim.x + threadIdx.x) >> 5;
    int lane = threadIdx.x & 31;
    if (e >= N_EDGES) return;
    size_t so = (size_t)src[e] * MLP_LD;
    size_t doff = (size_t)dst[e] * MLP_LD;
    int ipc = pc[e] * MLP_LD, irc = rc[e] * MLP_LD, ipf = pf[e] * MLP_LD;
    float n0 = num[(size_t)e * 5 + 0], n1 = num[(size_t)e * 5 + 1];
    float n2 = num[(size_t)e * 5 + 2], n3 = num[(size_t)e * 5 + 3];
    float n4 = num[(size_t)e * 5 + 4];
    const float* Wn = W0 + 280 * MLP_LD;
    #pragma unroll
    for (int t = 0; t < 10; t++) {
        int c = t * 32 + lane;
        float val = ns[so + c] + nd[doff + c] + tpc[ipc + c] + trc[irc + c] + tpf[ipf + c];
        val = fmaf(n0, Wn[c], val);
        val = fmaf(n1, Wn[MLP_LD + c], val);
        val = fmaf(n2, Wn[2 * MLP_LD + c], val);
        val = fmaf(n3, Wn[3 * MLP_LD + c], val);
        val = fmaf(n4, Wn[4 * MLP_LD + c], val);
        y[(size_t)e * MLP_LD + c] = fmaxf(val, 0.f);
    }
}

// ---------------- out init: fill with output bias ----------------
__global__ void out_init_kernel(float* __restrict__ out, const float* __restrict__ bo) {
    int idx = blockIdx.x * blockDim.x + threadIdx.x;
    if (idx < N_EDGES * 2) out[idx] = bo[idx & 1];
}

// ---------------- host ----------------
static inline int G(long long n) { return (int)((n + 255) / 256); }

extern "C" void kernel_launch(void* const* d_in, const int* in_sizes, int n_in,
                              void* d_out, int out_size) {
    const float* node_feats = (const float*)d_in[0];
    const float* numericals = (const float*)d_in[1];
    const float* W_emb = (const float*)d_in[2];
    const float* b_emb = (const float*)d_in[3];
    const float* WQ = (const float*)d_in[4];
    const float* bQ = (const float*)d_in[5];
    const float* WK = (const float*)d_in[6];
    const float* bK = (const float*)d_in[7];
    const float* WV = (const float*)d_in[8];
    const float* bV = (const float*)d_in[9];
    const float* WO = (const float*)d_in[10];
    const float* bO = (const float*)d_in[11];
    const float* ln1_g = (const float*)d_in[12];
    const float* ln1_b = (const float*)d_in[13];
    const float* ln2_g = (const float*)d_in[14];
    const float* ln2_b = (const float*)d_in[15];
    const float* W1 = (const float*)d_in[16];
    const float* b1 = (const float*)d_in[17];
    const float* W2 = (const float*)d_in[18];
    const float* b2 = (const float*)d_in[19];
    const float* curr_emb = (const float*)d_in[20];
    const float* pay_emb = (const float*)d_in[21];
    const float* mlp_Wh = (const float*)d_in[22];
    const float* mlp_bh = (const float*)d_in[23];
    const float* mlp_Wo = (const float*)d_in[24];
    const float* mlp_bo = (const float*)d_in[25];
    const int* src = (const int*)d_in[26];
    const int* dst = (const int*)d_in[27];
    const int* pc = (const int*)d_in[28];
    const int* rc = (const int*)d_in[29];
    const int* pf = (const int*)d_in[30];
    float* out = (float*)d_out;

    float *h, *x, *qkv, *attn, *tmp, *y0, *y1, *Wpad, *bpad, *Wopad;
    float *Wqkv, *bqkv, *ns, *nd, *tpc, *trc, *tpf, *zero;
    int *deg, *rowptr, *cursor, *srcs;
    cudaGetSymbolAddress((void**)&h, g_h);
    cudaGetSymbolAddress((void**)&x, g_x);
    cudaGetSymbolAddress((void**)&qkv, g_qkv);
    cudaGetSymbolAddress((void**)&attn, g_attn);
    cudaGetSymbolAddress((void**)&tmp, g_tmp);
    cudaGetSymbolAddress((void**)&y0, g_y0);
    cudaGetSymbolAddress((void**)&y1, g_y1);
    cudaGetSymbolAddress((void**)&Wpad, g_Wpad);
    cudaGetSymbolAddress((void**)&bpad, g_bpad);
    cudaGetSymbolAddress((void**)&Wopad, g_Wopad);
    cudaGetSymbolAddress((void**)&Wqkv, g_Wqkv);
    cudaGetSymbolAddress((void**)&bqkv, g_bqkv);
    cudaGetSymbolAddress((void**)&ns, g_ns);
    cudaGetSymbolAddress((void**)&nd, g_nd);
    cudaGetSymbolAddress((void**)&tpc, g_tpc);
    cudaGetSymbolAddress((void**)&trc, g_trc);
    cudaGetSymbolAddress((void**)&tpf, g_tpf);
    cudaGetSymbolAddress((void**)&zero, g_zero);
    cudaGetSymbolAddress((void**)&deg, g_deg);
    cudaGetSymbolAddress((void**)&rowptr, g_rowptr);
    cudaGetSymbolAddress((void**)&cursor, g_cursor);
    cudaGetSymbolAddress((void**)&srcs, g_srcs);

    // ---- one-time prep ----
    padW_kernel<<<G(3 * MLP_K * MLP_LD), 256>>>(mlp_Wh, Wpad);
    padb_kernel<<<G(3 * MLP_LD), 256>>>(mlp_bh, bpad, mlp_Wo, Wopad, zero);
    packqkv_kernel<<<G((long long)LAYERS * HID * 384), 256>>>(WQ, WK, WV, bQ, bK, bV,
                                                              Wqkv, bqkv);
    tables_kernel<<<G(37 * MLP_LD), 256>>>(curr_emb, pay_emb, Wpad, tpc, trc, tpf);

    // CSR build
    deg_zero_kernel<<<G(N_NODES), 256>>>(deg);
    deg_count_kernel<<<G(N_EDGES), 256>>>(dst, deg);
    scan_kernel<<<1, 1024>>>(deg, rowptr);
    cursor_kernel<<<G(N_NODES), 256>>>(rowptr, cursor);
    scatter_kernel<<<G(N_EDGES), 256>>>(src, dst, cursor, srcs);

    embed_kernel<<<G((long long)N_NODES * HID), 256>>>(node_feats, W_emb, b_emb, h);

    // node-pipeline GEMMs: 3xTF32 tensor cores, 256-thread BM128/BN128 blocks
    auto gemm = [&](const float* A, const float* W, const float* bias, const float* res,
                    float* C, int M, int K, int Ncols, int relu) {
        dim3 grid((Ncols + 127) / 128, (M + 127) / 128);
        mma3b_gemm_kernel<<<grid, 256>>>(A, W, bias, res, C, M, K, Ncols, relu);
    };

    for (int l = 0; l < LAYERS; l++) {
        const int WOFF = l * HID * HID, BOFF = l * HID;
        ln_kernel<<<G((long long)N_NODES * 32), 256>>>(h, ln1_g + BOFF, ln1_b + BOFF, x);
        gemm(x, Wqkv + l * HID * 384, bqkv + l * 384, nullptr, qkv, N_NODES, HID, 384, 0);
        attn_kernel<<<G((long long)N_NODES * 32), 256>>>(qkv, rowptr, srcs, attn);
        gemm(attn, WO + WOFF, bO + BOFF, h, h, N_NODES, HID, HID, 0);
        ln_kernel<<<G((long long)N_NODES * 32), 256>>>(h, ln2_g + BOFF, ln2_b + BOFF, x);
        gemm(x, W1 + WOFF, b1 + BOFF, nullptr, tmp, N_NODES, HID, HID, 1);
        gemm(tmp, W2 + WOFF, b2 + BOFF, h, h, N_NODES, HID, HID, 0);
    }

    // ---- edge classifier ----
    gemm(h, Wpad, bpad, nullptr, ns, N_NODES, HID, MLP_LD, 0);
    gemm(h, Wpad + 128 * MLP_LD, zero, nullptr, nd, N_NODES, HID, MLP_LD, 0);
    assemble_kernel<<<G((long long)N_EDGES * 32), 256>>>(
        ns, nd, tpc, trc, tpf, Wpad, numericals, src, dst, pc, rc, pf, y0);

    // layer 2: normal tf32 GEMM; layer 3: fused with output projection (atomicAdd)
    out_init_kernel<<<G((long long)N_EDGES * 2), 256>>>(out, mlp_bo);
    dim3 mgrid(GN / MBN, (N_EDGES + 127) / 128);
    mma_gemm_kernel<<<mgrid, 256>>>(y0, Wpad + 1 * MLP_K * MLP_LD, bpad + 1 * MLP_LD,
                                    y1, N_EDGES, nullptr, nullptr);
    mma_gemm_kernel<<<mgrid, 256>>>(y1, Wpad + 2 * MLP_K * MLP_LD, bpad + 2 * MLP_LD,
                                    nullptr, N_EDGES, Wopad, out);
}

// round 12
// speedup vs baseline: 1.2790x; 1.2790x over previous
#include <cuda_runtime.h>
#include <cstdint>
#include <cstddef>

#define N_NODES 20000
#define N_EDGES 200000
#define HID 128
#define NH 8
#define LAYERS 7
#define MLP_K 288      // padded K (285 -> 288)
#define MLP_LD 320     // padded row stride / N

// ---------------- scratch (static device globals) ----------------
__device__ float g_h[N_NODES * HID];
__device__ float g_x[N_NODES * HID];
__device__ float g_qkv[N_NODES * 384];
__device__ float g_attn[N_NODES * HID];
__device__ float g_tmp[N_NODES * HID];
__device__ float g_y0[(size_t)N_EDGES * MLP_LD];
__device__ float g_y1[(size_t)N_EDGES * MLP_LD];
__device__ float g_Wpad[3 * MLP_K * MLP_LD];
__device__ float g_bpad[3 * MLP_LD];
__device__ float g_Wopad[MLP_LD * 2];
__device__ float g_Wqkv[LAYERS * HID * 384];
__device__ float g_bqkv[LAYERS * 384];
__device__ float g_ns[(size_t)N_NODES * MLP_LD];
__device__ float g_nd[(size_t)N_NODES * MLP_LD];
__device__ float g_tpc[15 * MLP_LD];
__device__ float g_trc[15 * MLP_LD];
__device__ float g_tpf[7 * MLP_LD];
__device__ float g_zero[MLP_LD];
__device__ int   g_deg[N_NODES];
__device__ int   g_rowptr[N_NODES + 1];
__device__ int   g_cursor[N_NODES];
__device__ int   g_srcs[N_EDGES];

__device__ __forceinline__ float tf32r(float x) {
    unsigned u;
    asm("cvt.rna.tf32.f32 %0, %1;" : "=r"(u) : "f"(x));
    return __uint_as_float(u);
}

// ---------------- embedding ----------------
__global__ void embed_kernel(const float* __restrict__ nf, const float* __restrict__ We,
                             const float* __restrict__ be, float* __restrict__ h) {
    int idx = blockIdx.x * blockDim.x + threadIdx.x;
    if (idx >= N_NODES * HID) return;
    int n = idx >> 7, c = idx & 127;
    h[idx] = fmaf(nf[n * 2 + 0], We[c], fmaf(nf[n * 2 + 1], We[HID + c], be[c]));
}

// ---------------- LayerNorm: warp per node ----------------
__global__ void ln_kernel(const float* __restrict__ h, const float* __restrict__ g,
                          const float* __restrict__ b, float* __restrict__ x) {
    int node = (blockIdx.x * blockDim.x + threadIdx.x) >> 5;
    int lane = threadIdx.x & 31;
    if (node >= N_NODES) return;
    float4 v = *(const float4*)&h[node * HID + lane * 4];
    float s = v.x + v.y + v.z + v.w;
    #pragma unroll
    for (int o = 16; o; o >>= 1) s += __shfl_xor_sync(0xffffffffu, s, o);
    float mu = s * (1.0f / 128.0f);
    float dx = v.x - mu, dy = v.y - mu, dz = v.z - mu, dw = v.w - mu;
    float q = dx * dx + dy * dy + dz * dz + dw * dw;
    #pragma unroll
    for (int o = 16; o; o >>= 1) q += __shfl_xor_sync(0xffffffffu, q, o);
    float rs = rsqrtf(q * (1.0f / 128.0f) + 1e-5f);
    float4 gv = *(const float4*)&g[lane * 4];
    float4 bv = *(const float4*)&b[lane * 4];
    float4 o4;
    o4.x = fmaf(dx * rs, gv.x, bv.x);
    o4.y = fmaf(dy * rs, gv.y, bv.y);
    o4.z = fmaf(dz * rs, gv.z, bv.z);
    o4.w = fmaf(dw * rs, gv.w, bv.w);
    *(float4*)&x[node * HID + lane * 4] = o4;
}

// ---------------- tiled fp32 GEMM (node pipeline) ----------------
#define BM 128
#define BN 64
#define BK 16
#define TM 8
#define TN 4

__global__ __launch_bounds__(256)
void gemm_kernel(const float* __restrict__ A, const float* __restrict__ W,
                 const float* __restrict__ bias, const float* __restrict__ res,
                 float* __restrict__ C, int M, int K, int ldA, int N, int relu) {
    __shared__ float As[BK][BM + 4];
    __shared__ float Bs[BK][BN];
    int tid = threadIdx.x;
    int tx = tid & 15;
    int ty = tid >> 4;
    int rowBase = blockIdx.y * BM;
    int colBase = blockIdx.x * BN;

    float acc[TM][TN];
    #pragma unroll
    for (int i = 0; i < TM; i++)
        #pragma unroll
        for (int j = 0; j < TN; j++) acc[i][j] = 0.0f;

    for (int k0 = 0; k0 < K; k0 += BK) {
        #pragma unroll
        for (int it = 0; it < 2; it++) {
            int i4 = tid + it * 256;
            int r = i4 >> 2;
            int c4 = (i4 & 3) * 4;
            int gr = rowBase + r;
            float4 v = make_float4(0.f, 0.f, 0.f, 0.f);
            if (gr < M) v = *(const float4*)&A[(size_t)gr * ldA + k0 + c4];
            As[c4 + 0][r] = v.x; As[c4 + 1][r] = v.y;
            As[c4 + 2][r] = v.z; As[c4 + 3][r] = v.w;
        }
        {
            int r = tid >> 4;
            int c4 = (tid & 15) * 4;
            float4 v = *(const float4*)&W[(size_t)(k0 + r) * N + colBase + c4];
            *(float4*)&Bs[r][c4] = v;
        }
        __syncthreads();
        #pragma unroll
        for (int kk = 0; kk < BK; kk++) {
            float4 a0 = *(const float4*)&As[kk][ty * TM];
            float4 a1 = *(const float4*)&As[kk][ty * TM + 4];
            float4 b0 = *(const float4*)&Bs[kk][tx * TN];
            float a[TM] = {a0.x, a0.y, a0.z, a0.w, a1.x, a1.y, a1.z, a1.w};
            float b[TN] = {b0.x, b0.y, b0.z, b0.w};
            #pragma unroll
            for (int i = 0; i < TM; i++)
                #pragma unroll
                for (int j = 0; j < TN; j++)
                    acc[i][j] = fmaf(a[i], b[j], acc[i][j]);
        }
        __syncthreads();
    }

    int gc = colBase + tx * TN;
    float4 bv = *(const float4*)&bias[gc];
    #pragma unroll
    for (int i = 0; i < TM; i++) {
        int gr = rowBase + ty * TM + i;
        if (gr >= M) continue;
        float4 o;
        o.x = acc[i][0] + bv.x; o.y = acc[i][1] + bv.y;
        o.z = acc[i][2] + bv.z; o.w = acc[i][3] + bv.w;
        if (res) {
            float4 rv = *(const float4*)&res[(size_t)gr * N + gc];
            o.x += rv.x; o.y += rv.y; o.z += rv.z; o.w += rv.w;
        }
        if (relu) {
            o.x = fmaxf(o.x, 0.f); o.y = fmaxf(o.y, 0.f);
            o.z = fmaxf(o.z, 0.f); o.w = fmaxf(o.w, 0.f);
        }
        *(float4*)&C[(size_t)gr * N + gc] = o;
    }
}

// ---------------- tf32 tensor-core GEMM, single-pass BN=320 (MLP layers 2,3) -------
// C[M,320] = relu(A[M,320(K=288)] @ W[288,320] + bias).
// When WoT != nullptr: no C store; out[r,0:2] += relu(acc+bias) @ WoT
// (out pre-initialized with bo).
// 512 threads, 16 warps (4M x 4N), block tile 128x320, warp tile 32x80.
// BK=8, static smem 33.3KB (no cudaFuncSetAttribute needed), double-buffered.
#define GK 288
#define GN 320

__global__ __launch_bounds__(512)
void mlp_gemm_kernel(const float* __restrict__ A, const float* __restrict__ W,
                     const float* __restrict__ bias, float* __restrict__ C, int M,
                     const float* __restrict__ WoT, float* __restrict__ out) {
    __shared__ float As[2][128][12];    // 12,288 B
    __shared__ float Bs[2][8][328];     // 20,992 B

    int tid = threadIdx.x;
    int lane = tid & 31, warp = tid >> 5;
    int warpM = warp & 3, warpN = warp >> 2;     // 4 x 4
    int rowBase = blockIdx.x * 128;
    int gq = lane >> 2, tg = lane & 3;

    float acc[2][10][4];
    #pragma unroll
    for (int mi = 0; mi < 2; mi++)
        #pragma unroll
        for (int ni = 0; ni < 10; ni++)
            #pragma unroll
            for (int r = 0; r < 4; r++) acc[mi][ni][r] = 0.0f;

    // A staging: 128 rows x 8 floats = 256 float4; threads 0-255 only
    int ar = tid >> 1, ac = (tid & 1) * 4;
    bool aActive = tid < 256;
    bool av = aActive && (rowBase + ar) < M;
    // B staging: 8 x 320 = 640 float4; 2 iters (second partial: tid < 128)
    int br0 = tid / 80, bc0 = (tid % 80) * 4;
    int idx1 = tid + 512;
    bool bv1 = idx1 < 640;
    int br1 = idx1 / 80, bc1 = (idx1 % 80) * 4;

    float4 ra, rb0, rb1;

    auto loadG = [&](int k0) {
        ra = av ? *(const float4*)&A[(size_t)(rowBase + ar) * GN + k0 + ac]
                : make_float4(0.f, 0.f, 0.f, 0.f);
        rb0 = *(const float4*)&W[(size_t)(k0 + br0) * GN + bc0];
        rb1 = bv1 ? *(const float4*)&W[(size_t)(k0 + br1) * GN + bc1]
                  : make_float4(0.f, 0.f, 0.f, 0.f);
    };
    auto storeS = [&](int buf) {
        if (aActive) {
            float* ap = &As[buf][ar][ac];
            ap[0] = tf32r(ra.x); ap[1] = tf32r(ra.y);
            ap[2] = tf32r(ra.z); ap[3] = tf32r(ra.w);
        }
        {
            float* bp = &Bs[buf][br0][bc0];
            bp[0] = tf32r(rb0.x); bp[1] = tf32r(rb0.y);
            bp[2] = tf32r(rb0.z); bp[3] = tf32r(rb0.w);
        }
        if (bv1) {
            float* bp = &Bs[buf][br1][bc1];
            bp[0] = tf32r(rb1.x); bp[1] = tf32r(rb1.y);
            bp[2] = tf32r(rb1.z); bp[3] = tf32r(rb1.w);
        }
    };

    loadG(0);
    storeS(0);
    __syncthreads();

    const int NCHUNK = GK / 8;   // 36
    #pragma unroll 1
    for (int c = 0; c < NCHUNK; c++) {
        int cur = c & 1;
        if (c < NCHUNK - 1) loadG((c + 1) * 8);

        unsigned af[2][4];
        #pragma unroll
        for (int mi = 0; mi < 2; mi++) {
            int r = warpM * 32 + mi * 16 + gq;
            af[mi][0] = __float_as_uint(As[cur][r][tg]);
            af[mi][1] = __float_as_uint(As[cur][r + 8][tg]);
            af[mi][2] = __float_as_uint(As[cur][r][tg + 4]);
            af[mi][3] = __float_as_uint(As[cur][r + 8][tg + 4]);
        }
        #pragma unroll
        for (int ni = 0; ni < 10; ni++) {
            int bcol = warpN * 80 + ni * 8 + gq;
            unsigned b0 = __float_as_uint(Bs[cur][tg][bcol]);
            unsigned b1 = __float_as_uint(Bs[cur][tg + 4][bcol]);
            #pragma unroll
            for (int mi = 0; mi < 2; mi++) {
                asm volatile(
                    "mma.sync.aligned.m16n8k8.row.col.f32.tf32.tf32.f32 "
                    "{%0,%1,%2,%3},{%4,%5,%6,%7},{%8,%9},{%0,%1,%2,%3};"
                    : "+f"(acc[mi][ni][0]), "+f"(acc[mi][ni][1]),
                      "+f"(acc[mi][ni][2]), "+f"(acc[mi][ni][3])
                    : "r"(af[mi][0]), "r"(af[mi][1]), "r"(af[mi][2]), "r"(af[mi][3]),
                      "r"(b0), "r"(b1));
            }
        }

        if (c < NCHUNK - 1) {
            storeS(cur ^ 1);
            __syncthreads();
        }
    }

    if (WoT == nullptr) {
        // normal epilogue: relu(acc + bias) -> C
        #pragma unroll
        for (int ni = 0; ni < 10; ni++) {
            int gc = warpN * 80 + ni * 8 + 2 * tg;
            float2 bvv = *(const float2*)&bias[gc];
            #pragma unroll
            for (int mi = 0; mi < 2; mi++) {
                int r0 = rowBase + warpM * 32 + mi * 16 + gq;
                if (r0 < M) {
                    float2 o;
                    o.x = fmaxf(acc[mi][ni][0] + bvv.x, 0.f);
                    o.y = fmaxf(acc[mi][ni][1] + bvv.y, 0.f);
                    *(float2*)&C[(size_t)r0 * GN + gc] = o;
                }
                int r1 = r0 + 8;
                if (r1 < M) {
                    float2 o;
                    o.x = fmaxf(acc[mi][ni][2] + bvv.x, 0.f);
                    o.y = fmaxf(acc[mi][ni][3] + bvv.y, 0.f);
                    *(float2*)&C[(size_t)r1 * GN + gc] = o;
                }
            }
        }
    } else {
        // fused epilogue: out[r] += relu(acc+bias) @ WoT  (warp's 80 cols)
        float p[2][2][2];
        #pragma unroll
        for (int mi = 0; mi < 2; mi++) {
            p[mi][0][0] = 0.f; p[mi][0][1] = 0.f;
            p[mi][1][0] = 0.f; p[mi][1][1] = 0.f;
        }
        #pragma unroll
        for (int ni = 0; ni < 10; ni++) {
            int gc = warpN * 80 + ni * 8 + 2 * tg;
            float2 bvv = *(const float2*)&bias[gc];
            float w00 = WoT[gc * 2 + 0],       w01 = WoT[gc * 2 + 1];
            float w10 = WoT[(gc + 1) * 2 + 0], w11 = WoT[(gc + 1) * 2 + 1];
            #pragma unroll
            for (int mi = 0; mi < 2; mi++) {
                float ox = fmaxf(acc[mi][ni][0] + bvv.x, 0.f);
                float oy = fmaxf(acc[mi][ni][1] + bvv.y, 0.f);
                p[mi][0][0] = fmaf(ox, w00, fmaf(oy, w10, p[mi][0][0]));
                p[mi][0][1] = fmaf(ox, w01, fmaf(oy, w11, p[mi][0][1]));
                float zx = fmaxf(acc[mi][ni][2] + bvv.x, 0.f);
                float zy = fmaxf(acc[mi][ni][3] + bvv.y, 0.f);
                p[mi][1][0] = fmaf(zx, w00, fmaf(zy, w10, p[mi][1][0]));
                p[mi][1][1] = fmaf(zx, w01, fmaf(zy, w11, p[mi][1][1]));
            }
        }
        #pragma unroll
        for (int mi = 0; mi < 2; mi++) {
            #pragma unroll
            for (int hf = 0; hf < 2; hf++) {
                float v0 = p[mi][hf][0], v1 = p[mi][hf][1];
                v0 += __shfl_xor_sync(0xffffffffu, v0, 1);
                v0 += __shfl_xor_sync(0xffffffffu, v0, 2);
                v1 += __shfl_xor_sync(0xffffffffu, v1, 1);
                v1 += __shfl_xor_sync(0xffffffffu, v1, 2);
                if (tg == 0) {
                    int r = rowBase + warpM * 32 + mi * 16 + gq + hf * 8;
                    if (r < M) {
                        atomicAdd(&out[(size_t)r * 2 + 0], v0);
                        atomicAdd(&out[(size_t)r * 2 + 1], v1);
                    }
                }
            }
        }
    }
}

// ---------------- CSR build ----------------
__global__ void deg_zero_kernel(int* __restrict__ deg) {
    int i = blockIdx.x * blockDim.x + threadIdx.x;
    if (i < N_NODES) deg[i] = 0;
}
__global__ void deg_count_kernel(const int* __restrict__ dst, int* __restrict__ deg) {
    int e = blockIdx.x * blockDim.x + threadIdx.x;
    if (e < N_EDGES) atomicAdd(&deg[dst[e]], 1);
}
// exclusive scan; also initializes cursor = rowptr
__global__ void scan_kernel(const int* __restrict__ deg, int* __restrict__ rowptr,
                            int* __restrict__ cursor) {
    __shared__ int sums[1024];
    const int CH = (N_NODES + 1023) / 1024;   // 20
    int t = threadIdx.x;
    int base = t * CH;
    int local[CH];
    int s = 0;
    #pragma unroll
    for (int i = 0; i < CH; i++) {
        int idx = base + i;
        local[i] = (idx < N_NODES) ? deg[idx] : 0;
        s += local[i];
    }
    sums[t] = s;
    __syncthreads();
    for (int off = 1; off < 1024; off <<= 1) {
        int v = (t >= off) ? sums[t - off] : 0;
        __syncthreads();
        sums[t] += v;
        __syncthreads();
    }
    int run = sums[t] - s;
    #pragma unroll
    for (int i = 0; i < CH; i++) {
        int idx = base + i;
        if (idx < N_NODES) { rowptr[idx] = run; cursor[idx] = run; }
        run += local[i];
    }
    if (t == 1023) rowptr[N_NODES] = sums[1023];
}
__global__ void scatter_kernel(const int* __restrict__ src, const int* __restrict__ dst,
                               int* __restrict__ cur, int* __restrict__ srcs) {
    int e = blockIdx.x * blockDim.x + threadIdx.x;
    if (e >= N_EDGES) return;
    int pos = atomicAdd(&cur[dst[e]], 1);
    srcs[pos] = src[e];
}

// ---------------- fused attention: warp per dst node, online softmax ----------------
__global__ void attn_kernel(const float* __restrict__ qkv, const int* __restrict__ rowptr,
                            const int* __restrict__ srcs, float* __restrict__ attn) {
    int d = (blockIdx.x * blockDim.x + threadIdx.x) >> 5;
    int lane = threadIdx.x & 31;
    if (d >= N_NODES) return;
    int beg = rowptr[d], end = rowptr[d + 1];
    if (beg == end) {
        *(float4*)&attn[(size_t)d * HID + lane * 4] = make_float4(0.f, 0.f, 0.f, 0.f);
        return;
    }
    float4 qv = *(const float4*)&qkv[(size_t)d * 384 + lane * 4];
    float m = -3.4e38f, den = 0.f;
    float4 acc = make_float4(0.f, 0.f, 0.f, 0.f);
    for (int j = beg; j < end; j++) {
        int s = srcs[j];
        float4 kv = *(const float4*)&qkv[(size_t)s * 384 + 128 + lane * 4];
        float4 vv = *(const float4*)&qkv[(size_t)s * 384 + 256 + lane * 4];
        float p = qv.x * kv.x + qv.y * kv.y + qv.z * kv.z + qv.w * kv.w;
        p += __shfl_xor_sync(0xffffffffu, p, 1);
        p += __shfl_xor_sync(0xffffffffu, p, 2);
        float sc = p * 0.25f;
        float nm = fmaxf(m, sc);
        float scale = __expf(m - nm);
        float ex = __expf(sc - nm);
        acc.x = acc.x * scale + ex * vv.x;
        acc.y = acc.y * scale + ex * vv.y;
        acc.z = acc.z * scale + ex * vv.z;
        acc.w = acc.w * scale + ex * vv.w;
        den = den * scale + ex;
        m = nm;
    }
    float inv = 1.0f / den;
    float4 o = make_float4(acc.x * inv, acc.y * inv, acc.z * inv, acc.w * inv);
    *(float4*)&attn[(size_t)d * HID + lane * 4] = o;
}

// ---------------- weight prep ----------------
__global__ void padW_kernel(const float* __restrict__ Wh, float* __restrict__ Wpad) {
    int idx = blockIdx.x * blockDim.x + threadIdx.x;
    if (idx >= 3 * MLP_K * MLP_LD) return;
    int i = idx / (MLP_K * MLP_LD);
    int rem = idx - i * (MLP_K * MLP_LD);
    int r = rem / MLP_LD, c = rem - r * MLP_LD;
    Wpad[idx] = (r < 285 && c < 285) ? Wh[i * 285 * 285 + r * 285 + c] : 0.0f;
}

__global__ void padb_kernel(const float* __restrict__ bh, float* __restrict__ bpad,
                            const float* __restrict__ Wo, float* __restrict__ Wopad,
                            float* __restrict__ zero) {
    int idx = blockIdx.x * blockDim.x + threadIdx.x;
    if (idx < 3 * MLP_LD) {
        int i = idx / MLP_LD, c = idx - i * MLP_LD;
        bpad[idx] = (c < 285) ? bh[i * 285 + c] : 0.0f;
    }
    if (idx < MLP_LD * 2) {
        int r = idx >> 1;
        Wopad[idx] = (r < 285) ? Wo[idx] : 0.0f;
    }
    if (idx < MLP_LD) zero[idx] = 0.0f;
}

__global__ void packqkv_kernel(const float* __restrict__ WQ, const float* __restrict__ WK,
                               const float* __restrict__ WV, const float* __restrict__ bQ,
                               const float* __restrict__ bK, const float* __restrict__ bV,
                               float* __restrict__ Wqkv, float* __restrict__ bqkv) {
    int idx = blockIdx.x * blockDim.x + threadIdx.x;
    if (idx < LAYERS * HID * 384) {
        int l = idx / (HID * 384);
        int rem = idx - l * (HID * 384);
        int r = rem / 384, c = rem - r * 384;
        float v;
        if (c < 128)      v = WQ[l * HID * HID + r * HID + c];
        else if (c < 256) v = WK[l * HID * HID + r * HID + (c - 128)];
        else              v = WV[l * HID * HID + r * HID + (c - 256)];
        Wqkv[idx] = v;
    }
    if (idx < LAYERS * 384) {
        int l = idx / 384, c = idx - l * 384;
        float v;
        if (c < 128)      v = bQ[l * HID + c];
        else if (c < 256) v = bK[l * HID + (c - 128)];
        else              v = bV[l * HID + (c - 256)];
        bqkv[idx] = v;
    }
}

__global__ void tables_kernel(const float* __restrict__ ce, const float* __restrict__ pe,
                              const float* __restrict__ W0, float* __restrict__ tpc,
                              float* __restrict__ trc, float* __restrict__ tpf) {
    int idx = blockIdx.x * blockDim.x + threadIdx.x;
    if (idx >= 37 * MLP_LD) return;
    int i = idx / MLP_LD, c = idx - i * MLP_LD;
    if (i < 15) {
        float s = 0.f;
        #pragma unroll
        for (int k = 0; k < 8; k++) s = fmaf(ce[i * 8 + k], W0[(256 + k) * MLP_LD + c], s);
        tpc[i * MLP_LD + c] = s;
    } else if (i < 30) {
        int ii = i - 15;
        float s = 0.f;
        #pragma unroll
        for (int k = 0; k < 8; k++) s = fmaf(ce[ii * 8 + k], W0[(264 + k) * MLP_LD + c], s);
        trc[ii * MLP_LD + c] = s;
    } else {
        int ii = i - 30;
        float s = 0.f;
        #pragma unroll
        for (int k = 0; k < 8; k++) s = fmaf(pe[ii * 8 + k], W0[(272 + k) * MLP_LD + c], s);
        tpf[ii * MLP_LD + c] = s;
    }
}

// ---------------- MLP layer-1 assemble: warp per edge ----------------
__global__ void assemble_kernel(const float* __restrict__ ns, const float* __restrict__ nd,
                                const float* __restrict__ tpc, const float* __restrict__ trc,
                                const float* __restrict__ tpf, const float* __restrict__ W0,
                                const float* __restrict__ num, const int* __restrict__ src,
                                const int* __restrict__ dst, const int* __restrict__ pc,
                                const int* __restrict__ rc, const int* __restrict__ pf,
                                float* __restrict__ y) {
    int e = (blockIdx.x * blockDim.x + threadIdx.x) >> 5;
    int lane = threadIdx.x & 31;
    if (e >= N_EDGES) return;
    size_t so = (size_t)src[e] * MLP_LD;
    size_t doff = (size_t)dst[e] * MLP_LD;
    int ipc = pc[e] * MLP_LD, irc = rc[e] * MLP_LD, ipf = pf[e] * MLP_LD;
    float n0 = num[(size_t)e * 5 + 0], n1 = num[(size_t)e * 5 + 1];
    float n2 = num[(size_t)e * 5 + 2], n3 = num[(size_t)e * 5 + 3];
    float n4 = num[(size_t)e * 5 + 4];
    const float* Wn = W0 + 280 * MLP_LD;
    #pragma unroll
    for (int t = 0; t < 10; t++) {
        int c = t * 32 + lane;
        float val = ns[so + c] + nd[doff + c] + tpc[ipc + c] + trc[irc + c] + tpf[ipf + c];
        val = fmaf(n0, Wn[c], val);
        val = fmaf(n1, Wn[MLP_LD + c], val);
        val = fmaf(n2, Wn[2 * MLP_LD + c], val);
        val = fmaf(n3, Wn[3 * MLP_LD + c], val);
        val = fmaf(n4, Wn[4 * MLP_LD + c], val);
        y[(size_t)e * MLP_LD + c] = fmaxf(val, 0.f);
    }
}

// ---------------- out init: fill with output bias ----------------
__global__ void out_init_kernel(float* __restrict__ out, const float* __restrict__ bo) {
    int idx = blockIdx.x * blockDim.x + threadIdx.x;
    if (idx < N_EDGES * 2) out[idx] = bo[idx & 1];
}

// ---------------- host ----------------
static inline int G(long long n) { return (int)((n + 255) / 256); }

extern "C" void kernel_launch(void* const* d_in, const int* in_sizes, int n_in,
                              void* d_out, int out_size) {
    const float* node_feats = (const float*)d_in[0];
    const float* numericals = (const float*)d_in[1];
    const float* W_emb = (const float*)d_in[2];
    const float* b_emb = (const float*)d_in[3];
    const float* WQ = (const float*)d_in[4];
    const float* bQ = (const float*)d_in[5];
    const float* WK = (const float*)d_in[6];
    const float* bK = (const float*)d_in[7];
    const float* WV = (const float*)d_in[8];
    const float* bV = (const float*)d_in[9];
    const float* WO = (const float*)d_in[10];
    const float* bO = (const float*)d_in[11];
    const float* ln1_g = (const float*)d_in[12];
    const float* ln1_b = (const float*)d_in[13];
    const float* ln2_g = (const float*)d_in[14];
    const float* ln2_b = (const float*)d_in[15];
    const float* W1 = (const float*)d_in[16];
    const float* b1 = (const float*)d_in[17];
    const float* W2 = (const float*)d_in[18];
    const float* b2 = (const float*)d_in[19];
    const float* curr_emb = (const float*)d_in[20];
    const float* pay_emb = (const float*)d_in[21];
    const float* mlp_Wh = (const float*)d_in[22];
    const float* mlp_bh = (const float*)d_in[23];
    const float* mlp_Wo = (const float*)d_in[24];
    const float* mlp_bo = (const float*)d_in[25];
    const int* src = (const int*)d_in[26];
    const int* dst = (const int*)d_in[27];
    const int* pc = (const int*)d_in[28];
    const int* rc = (const int*)d_in[29];
    const int* pf = (const int*)d_in[30];
    float* out = (float*)d_out;

    float *h, *x, *qkv, *attn, *tmp, *y0, *y1, *Wpad, *bpad, *Wopad;
    float *Wqkv, *bqkv, *ns, *nd, *tpc, *trc, *tpf, *zero;
    int *deg, *rowptr, *cursor, *srcs;
    cudaGetSymbolAddress((void**)&h, g_h);
    cudaGetSymbolAddress((void**)&x, g_x);
    cudaGetSymbolAddress((void**)&qkv, g_qkv);
    cudaGetSymbolAddress((void**)&attn, g_attn);
    cudaGetSymbolAddress((void**)&tmp, g_tmp);
    cudaGetSymbolAddress((void**)&y0, g_y0);
    cudaGetSymbolAddress((void**)&y1, g_y1);
    cudaGetSymbolAddress((void**)&Wpad, g_Wpad);
    cudaGetSymbolAddress((void**)&bpad, g_bpad);
    cudaGetSymbolAddress((void**)&Wopad, g_Wopad);
    cudaGetSymbolAddress((void**)&Wqkv, g_Wqkv);
    cudaGetSymbolAddress((void**)&bqkv, g_bqkv);
    cudaGetSymbolAddress((void**)&ns, g_ns);
    cudaGetSymbolAddress((void**)&nd, g_nd);
    cudaGetSymbolAddress((void**)&tpc, g_tpc);
    cudaGetSymbolAddress((void**)&trc, g_trc);
    cudaGetSymbolAddress((void**)&tpf, g_tpf);
    cudaGetSymbolAddress((void**)&zero, g_zero);
    cudaGetSymbolAddress((void**)&deg, g_deg);
    cudaGetSymbolAddress((void**)&rowptr, g_rowptr);
    cudaGetSymbolAddress((void**)&cursor, g_cursor);
    cudaGetSymbolAddress((void**)&srcs, g_srcs);

    // ---- one-time prep ----
    padW_kernel<<<G(3 * MLP_K * MLP_LD), 256>>>(mlp_Wh, Wpad);
    padb_kernel<<<G(3 * MLP_LD), 256>>>(mlp_bh, bpad, mlp_Wo, Wopad, zero);
    packqkv_kernel<<<G((long long)LAYERS * HID * 384), 256>>>(WQ, WK, WV, bQ, bK, bV,
                                                              Wqkv, bqkv);
    tables_kernel<<<G(37 * MLP_LD), 256>>>(curr_emb, pay_emb, Wpad, tpc, trc, tpf);

    // CSR build
    deg_zero_kernel<<<G(N_NODES), 256>>>(deg);
    deg_count_kernel<<<G(N_EDGES), 256>>>(dst, deg);
    scan_kernel<<<1, 1024>>>(deg, rowptr, cursor);
    scatter_kernel<<<G(N_EDGES), 256>>>(src, dst, cursor, srcs);

    embed_kernel<<<G((long long)N_NODES * HID), 256>>>(node_feats, W_emb, b_emb, h);

    // node-pipeline GEMMs: SIMT fp32 (exact; proven fastest on this chip)
    auto gemm = [&](const float* A, const float* W, const float* bias, const float* res,
                    float* C, int M, int K, int ldA, int Ncols, int relu) {
        dim3 grid(Ncols / BN, (M + BM - 1) / BM);
        gemm_kernel<<<grid, 256>>>(A, W, bias, res, C, M, K, ldA, Ncols, relu);
    };

    for (int l = 0; l < LAYERS; l++) {
        const int WOFF = l * HID * HID, BOFF = l * HID;
        ln_kernel<<<G((long long)N_NODES * 32), 256>>>(h, ln1_g + BOFF, ln1_b + BOFF, x);
        gemm(x, Wqkv + l * HID * 384, bqkv + l * 384, nullptr, qkv,
             N_NODES, HID, HID, 384, 0);
        attn_kernel<<<G((long long)N_NODES * 32), 256>>>(qkv, rowptr, srcs, attn);
        gemm(attn, WO + WOFF, bO + BOFF, h, h, N_NODES, HID, HID, HID, 0);
        ln_kernel<<<G((long long)N_NODES * 32), 256>>>(h, ln2_g + BOFF, ln2_b + BOFF, x);
        gemm(x, W1 + WOFF, b1 + BOFF, nullptr, tmp, N_NODES, HID, HID, HID, 1);
        gemm(tmp, W2 + WOFF, b2 + BOFF, h, h, N_NODES, HID, HID, HID, 0);
    }

    // ---- edge classifier ----
    // layer 1 decomposed (exact fp32): per-node projections + tables + assemble
    gemm(h, Wpad, bpad, nullptr, ns, N_NODES, HID, HID, MLP_LD, 0);
    gemm(h, Wpad + 128 * MLP_LD, zero, nullptr, nd, N_NODES, HID, HID, MLP_LD, 0);
    assemble_kernel<<<G((long long)N_EDGES * 32), 256>>>(
        ns, nd, tpc, trc, tpf, Wpad, numericals, src, dst, pc, rc, pf, y0);

    // layers 2,3: single-pass tf32 GEMMs; layer 3 fused with output projection
    out_init_kernel<<<G((long long)N_EDGES * 2), 256>>>(out, mlp_bo);
    int mblocks = (N_EDGES + 127) / 128;
    mlp_gemm_kernel<<<mblocks, 512>>>(
        y0, Wpad + 1 * MLP_K * MLP_LD, bpad + 1 * MLP_LD, y1, N_EDGES, nullptr, nullptr);
    mlp_gemm_kernel<<<mblocks, 512>>>(
        y1, Wpad + 2 * MLP_K * MLP_LD, bpad + 2 * MLP_LD, nullptr, N_EDGES, Wopad, out);
}

// round 13
// speedup vs baseline: 1.5341x; 1.1995x over previous
#include <cuda_runtime.h>
#include <cuda_bf16.h>
#include <cstdint>
#include <cstddef>

#define N_NODES 20000
#define N_EDGES 200000
#define HID 128
#define NH 8
#define LAYERS 7
#define MLP_K 288      // padded K (285 -> 288)
#define MLP_LD 320     // padded row stride / N

// ---------------- scratch (static device globals) ----------------
__device__ float g_h[N_NODES * HID];
__device__ float g_x[N_NODES * HID];
__device__ float g_qkv[N_NODES * 384];
__device__ float g_attn[N_NODES * HID];
__device__ float g_tmp[N_NODES * HID];
__device__ float g_y0[(size_t)N_EDGES * MLP_LD];
__device__ float g_y1[(size_t)N_EDGES * MLP_LD];
__device__ float g_Wpad[3 * MLP_K * MLP_LD];
__device__ float g_bpad[3 * MLP_LD];
__device__ float g_Wopad[MLP_LD * 2];
__device__ float g_Wqkv[LAYERS * HID * 384];
__device__ float g_bqkv[LAYERS * 384];
__device__ float g_ns[(size_t)N_NODES * MLP_LD];
__device__ float g_nd[(size_t)N_NODES * MLP_LD];
__device__ float g_tpc[15 * MLP_LD];
__device__ float g_trc[15 * MLP_LD];
__device__ float g_tpf[7 * MLP_LD];
__device__ float g_zero[MLP_LD];
__device__ int   g_deg[N_NODES];
__device__ int   g_rowptr[N_NODES + 1];
__device__ int   g_cursor[N_NODES];
__device__ int   g_srcs[N_EDGES];
// packed bf16 hi/lo weights (word = 2 k-consecutive bf16)
__device__ unsigned g_Wqkv_h[LAYERS * 64 * 384], g_Wqkv_l[LAYERS * 64 * 384];
__device__ unsigned g_WO_h[LAYERS * 64 * 128],   g_WO_l[LAYERS * 64 * 128];
__device__ unsigned g_W1_h[LAYERS * 64 * 128],   g_W1_l[LAYERS * 64 * 128];
__device__ unsigned g_W2_h[LAYERS * 64 * 128],   g_W2_l[LAYERS * 64 * 128];
__device__ unsigned g_Wns_h[2 * 64 * 384],       g_Wns_l[2 * 64 * 384];

__device__ __forceinline__ float tf32r(float x) {
    unsigned u;
    asm("cvt.rna.tf32.f32 %0, %1;" : "=r"(u) : "f"(x));
    return __uint_as_float(u);
}

__device__ __forceinline__ unsigned pack2_hi(float f0, float f1, float& r0, float& r1) {
    __nv_bfloat16 h0 = __float2bfloat16_rn(f0);
    __nv_bfloat16 h1 = __float2bfloat16_rn(f1);
    r0 = f0 - __bfloat162float(h0);
    r1 = f1 - __bfloat162float(h1);
    __nv_bfloat162 p; p.x = h0; p.y = h1;
    return *reinterpret_cast<unsigned*>(&p);
}
__device__ __forceinline__ unsigned pack2(float f0, float f1) {
    __nv_bfloat162 p = __floats2bfloat162_rn(f0, f1);
    return *reinterpret_cast<unsigned*>(&p);
}

#define BF16MMA(ACC, A0, A1, A2, A3, B0, B1) \
    asm volatile("mma.sync.aligned.m16n8k16.row.col.f32.bf16.bf16.f32 " \
        "{%0,%1,%2,%3},{%4,%5,%6,%7},{%8,%9},{%0,%1,%2,%3};" \
        : "+f"((ACC)[0]), "+f"((ACC)[1]), "+f"((ACC)[2]), "+f"((ACC)[3]) \
        : "r"(A0), "r"(A1), "r"(A2), "r"(A3), "r"(B0), "r"(B1))

// ---------------- embedding ----------------
__global__ void embed_kernel(const float* __restrict__ nf, const float* __restrict__ We,
                             const float* __restrict__ be, float* __restrict__ h) {
    int idx = blockIdx.x * blockDim.x + threadIdx.x;
    if (idx >= N_NODES * HID) return;
    int n = idx >> 7, c = idx & 127;
    h[idx] = fmaf(nf[n * 2 + 0], We[c], fmaf(nf[n * 2 + 1], We[HID + c], be[c]));
}

// ---------------- LayerNorm: warp per node ----------------
__global__ void ln_kernel(const float* __restrict__ h, const float* __restrict__ g,
                          const float* __restrict__ b, float* __restrict__ x) {
    int node = (blockIdx.x * blockDim.x + threadIdx.x) >> 5;
    int lane = threadIdx.x & 31;
    if (node >= N_NODES) return;
    float4 v = *(const float4*)&h[node * HID + lane * 4];
    float s = v.x + v.y + v.z + v.w;
    #pragma unroll
    for (int o = 16; o; o >>= 1) s += __shfl_xor_sync(0xffffffffu, s, o);
    float mu = s * (1.0f / 128.0f);
    float dx = v.x - mu, dy = v.y - mu, dz = v.z - mu, dw = v.w - mu;
    float q = dx * dx + dy * dy + dz * dz + dw * dw;
    #pragma unroll
    for (int o = 16; o; o >>= 1) q += __shfl_xor_sync(0xffffffffu, q, o);
    float rs = rsqrtf(q * (1.0f / 128.0f) + 1e-5f);
    float4 gv = *(const float4*)&g[lane * 4];
    float4 bv = *(const float4*)&b[lane * 4];
    float4 o4;
    o4.x = fmaf(dx * rs, gv.x, bv.x);
    o4.y = fmaf(dy * rs, gv.y, bv.y);
    o4.z = fmaf(dz * rs, gv.z, bv.z);
    o4.w = fmaf(dw * rs, gv.w, bv.w);
    *(float4*)&x[node * HID + lane * 4] = o4;
}

// ---------------- weight bf16 hi/lo packing ----------------
// src: nmat matrices of [128][Nsrc] row-major -> dh/dl [nmat][64][Ndst] words
__global__ void packw_kernel(const float* __restrict__ src, unsigned* __restrict__ dh,
                             unsigned* __restrict__ dl, int nmat, int Nsrc, int Ndst) {
    int idx = blockIdx.x * blockDim.x + threadIdx.x;
    int total = nmat * 64 * Ndst;
    if (idx >= total) return;
    int mat = idx / (64 * Ndst);
    int rem = idx - mat * 64 * Ndst;
    int w = rem / Ndst, n = rem - w * Ndst;
    const float* s = src + (size_t)mat * 128 * Nsrc;
    float f0 = (n < Nsrc) ? s[(size_t)(2 * w) * Nsrc + n] : 0.f;
    float f1 = (n < Nsrc) ? s[(size_t)(2 * w + 1) * Nsrc + n] : 0.f;
    float r0, r1;
    dh[idx] = pack2_hi(f0, f1, r0, r1);
    dl[idx] = pack2(r0, r1);
}

// ---------------- 3xBF16-split tensor GEMM (node pipeline; fp32-near accuracy) ------
// C[M,N] = act(A[M,128] @ W[128,N] + bias [+ res]); N % 4 == 0.
// W pre-packed bf16 hi/lo words [64][ldw]. 256 threads, 8 warps (2M x 4N),
// block tile 128x128, warp tile 64x32, BK=16 (one m16n8k16 per chunk).
__global__ void __launch_bounds__(256, 2)
bf16_gemm_kernel(const float* __restrict__ A,
                 const unsigned* __restrict__ Wh, const unsigned* __restrict__ Wl,
                 int ldw, const float* __restrict__ bias, const float* __restrict__ res,
                 float* __restrict__ C, int M, int N, int relu) {
    __shared__ unsigned Ash[2][128][12], Asl[2][128][12];   // 8 words + 4 pad
    __shared__ unsigned Bsh[2][8][136],  Bsl[2][8][136];    // 128 words + 8 pad

    int tid = threadIdx.x;
    int lane = tid & 31, warp = tid >> 5;
    int warpM = warp & 1, warpN = warp >> 1;     // 2 x 4
    int rowBase = blockIdx.y * 128, colBase = blockIdx.x * 128;
    int gq = lane >> 2, tg = lane & 3;

    float acc[4][4][4];
    #pragma unroll
    for (int mi = 0; mi < 4; mi++)
        #pragma unroll
        for (int ni = 0; ni < 4; ni++)
            #pragma unroll
            for (int r = 0; r < 4; r++) acc[mi][ni][r] = 0.0f;

    // A staging: 128 rows x 4 float4; 2 iters
    int ar[2], aw[2]; bool av[2];
    #pragma unroll
    for (int it = 0; it < 2; it++) {
        int idx = tid + it * 256;
        ar[it] = idx >> 2;
        aw[it] = (idx & 3) * 2;       // word offset within 8-word chunk row
        av[it] = (rowBase + ar[it]) < M;
    }
    // B staging: 8 word-rows x 128 words; uint4 per thread
    int bw = tid >> 5;                // 0..7
    int bn4 = lane * 4;               // 0..124

    float4 ra[2]; uint4 rbh, rbl;
    auto loadG = [&](int k0) {
        #pragma unroll
        for (int it = 0; it < 2; it++)
            ra[it] = av[it]
                ? *(const float4*)&A[(size_t)(rowBase + ar[it]) * 128 + k0 + aw[it] * 2]
                : make_float4(0.f, 0.f, 0.f, 0.f);
        int wrow = (k0 >> 1) + bw;
        rbh = *(const uint4*)&Wh[(size_t)wrow * ldw + colBase + bn4];
        rbl = *(const uint4*)&Wl[(size_t)wrow * ldw + colBase + bn4];
    };
    auto storeS = [&](int buf) {
        #pragma unroll
        for (int it = 0; it < 2; it++) {
            float r0, r1, r2, r3;
            unsigned h01 = pack2_hi(ra[it].x, ra[it].y, r0, r1);
            unsigned h23 = pack2_hi(ra[it].z, ra[it].w, r2, r3);
            Ash[buf][ar[it]][aw[it] + 0] = h01;
            Ash[buf][ar[it]][aw[it] + 1] = h23;
            Asl[buf][ar[it]][aw[it] + 0] = pack2(r0, r1);
            Asl[buf][ar[it]][aw[it] + 1] = pack2(r2, r3);
        }
        *(uint4*)&Bsh[buf][bw][bn4] = rbh;
        *(uint4*)&Bsl[buf][bw][bn4] = rbl;
    };

    loadG(0);
    storeS(0);
    __syncthreads();

    #pragma unroll 1
    for (int c = 0; c < 8; c++) {        // K = 128 = 8 x 16
        int cur = c & 1;
        if (c < 7) loadG((c + 1) * 16);

        unsigned bh0[4], bh1[4], bl0[4], bl1[4];
        #pragma unroll
        for (int ni = 0; ni < 4; ni++) {
            int bc = warpN * 32 + ni * 8 + gq;
            bh0[ni] = Bsh[cur][tg][bc]; bh1[ni] = Bsh[cur][tg + 4][bc];
            bl0[ni] = Bsl[cur][tg][bc]; bl1[ni] = Bsl[cur][tg + 4][bc];
        }
        #pragma unroll
        for (int mi = 0; mi < 4; mi++) {
            int r = warpM * 64 + mi * 16 + gq;
            unsigned ah0 = Ash[cur][r][tg],     ah1 = Ash[cur][r + 8][tg];
            unsigned ah2 = Ash[cur][r][tg + 4], ah3 = Ash[cur][r + 8][tg + 4];
            unsigned al0 = Asl[cur][r][tg],     al1 = Asl[cur][r + 8][tg];
            unsigned al2 = Asl[cur][r][tg + 4], al3 = Asl[cur][r + 8][tg + 4];
            #pragma unroll
            for (int ni = 0; ni < 4; ni++) {
                BF16MMA(acc[mi][ni], ah0, ah1, ah2, ah3, bh0[ni], bh1[ni]);
                BF16MMA(acc[mi][ni], al0, al1, al2, al3, bh0[ni], bh1[ni]);
                BF16MMA(acc[mi][ni], ah0, ah1, ah2, ah3, bl0[ni], bl1[ni]);
            }
        }
        if (c < 7) {
            storeS(cur ^ 1);
            __syncthreads();
        }
    }

    // epilogue: bias [+res] [+relu]
    #pragma unroll
    for (int ni = 0; ni < 4; ni++) {
        int gc = colBase + warpN * 32 + ni * 8 + 2 * tg;
        if (gc >= N) continue;
        float2 bv = *(const float2*)&bias[gc];
        #pragma unroll
        for (int mi = 0; mi < 4; mi++) {
            int r0 = rowBase + warpM * 64 + mi * 16 + gq;
            if (r0 < M) {
                float2 o;
                o.x = acc[mi][ni][0] + bv.x;
                o.y = acc[mi][ni][1] + bv.y;
                if (res) {
                    float2 rv = *(const float2*)&res[(size_t)r0 * N + gc];
                    o.x += rv.x; o.y += rv.y;
                }
                if (relu) { o.x = fmaxf(o.x, 0.f); o.y = fmaxf(o.y, 0.f); }
                *(float2*)&C[(size_t)r0 * N + gc] = o;
            }
            int r1 = r0 + 8;
            if (r1 < M) {
                float2 o;
                o.x = acc[mi][ni][2] + bv.x;
                o.y = acc[mi][ni][3] + bv.y;
                if (res) {
                    float2 rv = *(const float2*)&res[(size_t)r1 * N + gc];
                    o.x += rv.x; o.y += rv.y;
                }
                if (relu) { o.x = fmaxf(o.x, 0.f); o.y = fmaxf(o.y, 0.f); }
                *(float2*)&C[(size_t)r1 * N + gc] = o;
            }
        }
    }
}

// ---------------- tf32 tensor-core GEMM, single-pass BN=320 (MLP layers 2,3) -------
#define GK 288
#define GN 320

__global__ __launch_bounds__(512)
void mlp_gemm_kernel(const float* __restrict__ A, const float* __restrict__ W,
                     const float* __restrict__ bias, float* __restrict__ C, int M,
                     const float* __restrict__ WoT, float* __restrict__ out) {
    __shared__ float As[2][128][12];
    __shared__ float Bs[2][8][328];

    int tid = threadIdx.x;
    int lane = tid & 31, warp = tid >> 5;
    int warpM = warp & 3, warpN = warp >> 2;     // 4 x 4
    int rowBase = blockIdx.x * 128;
    int gq = lane >> 2, tg = lane & 3;

    float acc[2][10][4];
    #pragma unroll
    for (int mi = 0; mi < 2; mi++)
        #pragma unroll
        for (int ni = 0; ni < 10; ni++)
            #pragma unroll
            for (int r = 0; r < 4; r++) acc[mi][ni][r] = 0.0f;

    int ar = tid >> 1, ac = (tid & 1) * 4;
    bool aActive = tid < 256;
    bool av = aActive && (rowBase + ar) < M;
    int br0 = tid / 80, bc0 = (tid % 80) * 4;
    int idx1 = tid + 512;
    bool bv1 = idx1 < 640;
    int br1 = idx1 / 80, bc1 = (idx1 % 80) * 4;

    float4 ra, rb0, rb1;

    auto loadG = [&](int k0) {
        ra = av ? *(const float4*)&A[(size_t)(rowBase + ar) * GN + k0 + ac]
                : make_float4(0.f, 0.f, 0.f, 0.f);
        rb0 = *(const float4*)&W[(size_t)(k0 + br0) * GN + bc0];
        rb1 = bv1 ? *(const float4*)&W[(size_t)(k0 + br1) * GN + bc1]
                  : make_float4(0.f, 0.f, 0.f, 0.f);
    };
    auto storeS = [&](int buf) {
        if (aActive) {
            float* ap = &As[buf][ar][ac];
            ap[0] = tf32r(ra.x); ap[1] = tf32r(ra.y);
            ap[2] = tf32r(ra.z); ap[3] = tf32r(ra.w);
        }
        {
            float* bp = &Bs[buf][br0][bc0];
            bp[0] = tf32r(rb0.x); bp[1] = tf32r(rb0.y);
            bp[2] = tf32r(rb0.z); bp[3] = tf32r(rb0.w);
        }
        if (bv1) {
            float* bp = &Bs[buf][br1][bc1];
            bp[0] = tf32r(rb1.x); bp[1] = tf32r(rb1.y);
            bp[2] = tf32r(rb1.z); bp[3] = tf32r(rb1.w);
        }
    };

    loadG(0);
    storeS(0);
    __syncthreads();

    const int NCHUNK = GK / 8;   // 36
    #pragma unroll 1
    for (int c = 0; c < NCHUNK; c++) {
        int cur = c & 1;
        if (c < NCHUNK - 1) loadG((c + 1) * 8);

        unsigned af[2][4];
        #pragma unroll
        for (int mi = 0; mi < 2; mi++) {
            int r = warpM * 32 + mi * 16 + gq;
            af[mi][0] = __float_as_uint(As[cur][r][tg]);
            af[mi][1] = __float_as_uint(As[cur][r + 8][tg]);
            af[mi][2] = __float_as_uint(As[cur][r][tg + 4]);
            af[mi][3] = __float_as_uint(As[cur][r + 8][tg + 4]);
        }
        #pragma unroll
        for (int ni = 0; ni < 10; ni++) {
            int bcol = warpN * 80 + ni * 8 + gq;
            unsigned b0 = __float_as_uint(Bs[cur][tg][bcol]);
            unsigned b1 = __float_as_uint(Bs[cur][tg + 4][bcol]);
            #pragma unroll
            for (int mi = 0; mi < 2; mi++) {
                asm volatile(
                    "mma.sync.aligned.m16n8k8.row.col.f32.tf32.tf32.f32 "
                    "{%0,%1,%2,%3},{%4,%5,%6,%7},{%8,%9},{%0,%1,%2,%3};"
                    : "+f"(acc[mi][ni][0]), "+f"(acc[mi][ni][1]),
                      "+f"(acc[mi][ni][2]), "+f"(acc[mi][ni][3])
                    : "r"(af[mi][0]), "r"(af[mi][1]), "r"(af[mi][2]), "r"(af[mi][3]),
                      "r"(b0), "r"(b1));
            }
        }

        if (c < NCHUNK - 1) {
            storeS(cur ^ 1);
            __syncthreads();
        }
    }

    if (WoT == nullptr) {
        #pragma unroll
        for (int ni = 0; ni < 10; ni++) {
            int gc = warpN * 80 + ni * 8 + 2 * tg;
            float2 bvv = *(const float2*)&bias[gc];
            #pragma unroll
            for (int mi = 0; mi < 2; mi++) {
                int r0 = rowBase + warpM * 32 + mi * 16 + gq;
                if (r0 < M) {
                    float2 o;
                    o.x = fmaxf(acc[mi][ni][0] + bvv.x, 0.f);
                    o.y = fmaxf(acc[mi][ni][1] + bvv.y, 0.f);
                    *(float2*)&C[(size_t)r0 * GN + gc] = o;
                }
                int r1 = r0 + 8;
                if (r1 < M) {
                    float2 o;
                    o.x = fmaxf(acc[mi][ni][2] + bvv.x, 0.f);
                    o.y = fmaxf(acc[mi][ni][3] + bvv.y, 0.f);
                    *(float2*)&C[(size_t)r1 * GN + gc] = o;
                }
            }
        }
    } else {
        float p[2][2][2];
        #pragma unroll
        for (int mi = 0; mi < 2; mi++) {
            p[mi][0][0] = 0.f; p[mi][0][1] = 0.f;
            p[mi][1][0] = 0.f; p[mi][1][1] = 0.f;
        }
        #pragma unroll
        for (int ni = 0; ni < 10; ni++) {
            int gc = warpN * 80 + ni * 8 + 2 * tg;
            float2 bvv = *(const float2*)&bias[gc];
            float w00 = WoT[gc * 2 + 0],       w01 = WoT[gc * 2 + 1];
            float w10 = WoT[(gc + 1) * 2 + 0], w11 = WoT[(gc + 1) * 2 + 1];
            #pragma unroll
            for (int mi = 0; mi < 2; mi++) {
                float ox = fmaxf(acc[mi][ni][0] + bvv.x, 0.f);
                float oy = fmaxf(acc[mi][ni][1] + bvv.y, 0.f);
                p[mi][0][0] = fmaf(ox, w00, fmaf(oy, w10, p[mi][0][0]));
                p[mi][0][1] = fmaf(ox, w01, fmaf(oy, w11, p[mi][0][1]));
                float zx = fmaxf(acc[mi][ni][2] + bvv.x, 0.f);
                float zy = fmaxf(acc[mi][ni][3] + bvv.y, 0.f);
                p[mi][1][0] = fmaf(zx, w00, fmaf(zy, w10, p[mi][1][0]));
                p[mi][1][1] = fmaf(zx, w01, fmaf(zy, w11, p[mi][1][1]));
            }
        }
        #pragma unroll
        for (int mi = 0; mi < 2; mi++) {
            #pragma unroll
            for (int hf = 0; hf < 2; hf++) {
                float v0 = p[mi][hf][0], v1 = p[mi][hf][1];
                v0 += __shfl_xor_sync(0xffffffffu, v0, 1);
                v0 += __shfl_xor_sync(0xffffffffu, v0, 2);
                v1 += __shfl_xor_sync(0xffffffffu, v1, 1);
                v1 += __shfl_xor_sync(0xffffffffu, v1, 2);
                if (tg == 0) {
                    int r = rowBase + warpM * 32 + mi * 16 + gq + hf * 8;
                    if (r < M) {
                        atomicAdd(&out[(size_t)r * 2 + 0], v0);
                        atomicAdd(&out[(size_t)r * 2 + 1], v1);
                    }
                }
            }
        }
    }
}

// ---------------- CSR build ----------------
__global__ void deg_zero_kernel(int* __restrict__ deg) {
    int i = blockIdx.x * blockDim.x + threadIdx.x;
    if (i < N_NODES) deg[i] = 0;
}
__global__ void deg_count_kernel(const int* __restrict__ dst, int* __restrict__ deg) {
    int e = blockIdx.x * blockDim.x + threadIdx.x;
    if (e < N_EDGES) atomicAdd(&deg[dst[e]], 1);
}
__global__ void scan_kernel(const int* __restrict__ deg, int* __restrict__ rowptr,
                            int* __restrict__ cursor) {
    __shared__ int sums[1024];
    const int CH = (N_NODES + 1023) / 1024;   // 20
    int t = threadIdx.x;
    int base = t * CH;
    int local[CH];
    int s = 0;
    #pragma unroll
    for (int i = 0; i < CH; i++) {
        int idx = base + i;
        local[i] = (idx < N_NODES) ? deg[idx] : 0;
        s += local[i];
    }
    sums[t] = s;
    __syncthreads();
    for (int off = 1; off < 1024; off <<= 1) {
        int v = (t >= off) ? sums[t - off] : 0;
        __syncthreads();
        sums[t] += v;
        __syncthreads();
    }
    int run = sums[t] - s;
    #pragma unroll
    for (int i = 0; i < CH; i++) {
        int idx = base + i;
        if (idx < N_NODES) { rowptr[idx] = run; cursor[idx] = run; }
        run += local[i];
    }
    if (t == 1023) rowptr[N_NODES] = sums[1023];
}
__global__ void scatter_kernel(const int* __restrict__ src, const int* __restrict__ dst,
                               int* __restrict__ cur, int* __restrict__ srcs) {
    int e = blockIdx.x * blockDim.x + threadIdx.x;
    if (e >= N_EDGES) return;
    int pos = atomicAdd(&cur[dst[e]], 1);
    srcs[pos] = src[e];
}

// ---------------- fused attention: warp per dst node, online softmax ----------------
__global__ void attn_kernel(const float* __restrict__ qkv, const int* __restrict__ rowptr,
                            const int* __restrict__ srcs, float* __restrict__ attn) {
    int d = (blockIdx.x * blockDim.x + threadIdx.x) >> 5;
    int lane = threadIdx.x & 31;
    if (d >= N_NODES) return;
    int beg = rowptr[d], end = rowptr[d + 1];
    if (beg == end) {
        *(float4*)&attn[(size_t)d * HID + lane * 4] = make_float4(0.f, 0.f, 0.f, 0.f);
        return;
    }
    float4 qv = *(const float4*)&qkv[(size_t)d * 384 + lane * 4];
    float m = -3.4e38f, den = 0.f;
    float4 acc = make_float4(0.f, 0.f, 0.f, 0.f);
    for (int j = beg; j < end; j++) {
        int s = srcs[j];
        float4 kv = *(const float4*)&qkv[(size_t)s * 384 + 128 + lane * 4];
        float4 vv = *(const float4*)&qkv[(size_t)s * 384 + 256 + lane * 4];
        float p = qv.x * kv.x + qv.y * kv.y + qv.z * kv.z + qv.w * kv.w;
        p += __shfl_xor_sync(0xffffffffu, p, 1);
        p += __shfl_xor_sync(0xffffffffu, p, 2);
        float sc = p * 0.25f;
        float nm = fmaxf(m, sc);
        float scale = __expf(m - nm);
        float ex = __expf(sc - nm);
        acc.x = acc.x * scale + ex * vv.x;
        acc.y = acc.y * scale + ex * vv.y;
        acc.z = acc.z * scale + ex * vv.z;
        acc.w = acc.w * scale + ex * vv.w;
        den = den * scale + ex;
        m = nm;
    }
    float inv = 1.0f / den;
    float4 o = make_float4(acc.x * inv, acc.y * inv, acc.z * inv, acc.w * inv);
    *(float4*)&attn[(size_t)d * HID + lane * 4] = o;
}

// ---------------- weight prep ----------------
__global__ void padW_kernel(const float* __restrict__ Wh, float* __restrict__ Wpad) {
    int idx = blockIdx.x * blockDim.x + threadIdx.x;
    if (idx >= 3 * MLP_K * MLP_LD) return;
    int i = idx / (MLP_K * MLP_LD);
    int rem = idx - i * (MLP_K * MLP_LD);
    int r = rem / MLP_LD, c = rem - r * MLP_LD;
    Wpad[idx] = (r < 285 && c < 285) ? Wh[i * 285 * 285 + r * 285 + c] : 0.0f;
}

__global__ void padb_kernel(const float* __restrict__ bh, float* __restrict__ bpad,
                            const float* __restrict__ Wo, float* __restrict__ Wopad,
                            float* __restrict__ zero) {
    int idx = blockIdx.x * blockDim.x + threadIdx.x;
    if (idx < 3 * MLP_LD) {
        int i = idx / MLP_LD, c = idx - i * MLP_LD;
        bpad[idx] = (c < 285) ? bh[i * 285 + c] : 0.0f;
    }
    if (idx < MLP_LD * 2) {
        int r = idx >> 1;
        Wopad[idx] = (r < 285) ? Wo[idx] : 0.0f;
    }
    if (idx < MLP_LD) zero[idx] = 0.0f;
}

__global__ void packqkv_kernel(const float* __restrict__ WQ, const float* __restrict__ WK,
                               const float* __restrict__ WV, const float* __restrict__ bQ,
                               const float* __restrict__ bK, const float* __restrict__ bV,
                               float* __restrict__ Wqkv, float* __restrict__ bqkv) {
    int idx = blockIdx.x * blockDim.x + threadIdx.x;
    if (idx < LAYERS * HID * 384) {
        int l = idx / (HID * 384);
        int rem = idx - l * (HID * 384);
        int r = rem / 384, c = rem - r * 384;
        float v;
        if (c < 128)      v = WQ[l * HID * HID + r * HID + c];
        else if (c < 256) v = WK[l * HID * HID + r * HID + (c - 128)];
        else              v = WV[l * HID * HID + r * HID + (c - 256)];
        Wqkv[idx] = v;
    }
    if (idx < LAYERS * 384) {
        int l = idx / 384, c = idx - l * 384;
        float v;
        if (c < 128)      v = bQ[l * HID + c];
        else if (c < 256) v = bK[l * HID + (c - 128)];
        else              v = bV[l * HID + (c - 256)];
        bqkv[idx] = v;
    }
}

__global__ void tables_kernel(const float* __restrict__ ce, const float* __restrict__ pe,
                              const float* __restrict__ W0, float* __restrict__ tpc,
                              float* __restrict__ trc, float* __restrict__ tpf) {
    int idx = blockIdx.x * blockDim.x + threadIdx.x;
    if (idx >= 37 * MLP_LD) return;
    int i = idx / MLP_LD, c = idx - i * MLP_LD;
    if (i < 15) {
        float s = 0.f;
        #pragma unroll
        for (int k = 0; k < 8; k++) s = fmaf(ce[i * 8 + k], W0[(256 + k) * MLP_LD + c], s);
        tpc[i * MLP_LD + c] = s;
    } else if (i < 30) {
        int ii = i - 15;
        float s = 0.f;
        #pragma unroll
        for (int k = 0; k < 8; k++) s = fmaf(ce[ii * 8 + k], W0[(264 + k) * MLP_LD + c], s);
        trc[ii * MLP_LD + c] = s;
    } else {
        int ii = i - 30;
        float s = 0.f;
        #pragma unroll
        for (int k = 0; k < 8; k++) s = fmaf(pe[ii * 8 + k], W0[(272 + k) * MLP_LD + c], s);
        tpf[ii * MLP_LD + c] = s;
    }
}

// ---------------- MLP layer-1 assemble: warp per edge ----------------
__global__ void assemble_kernel(const float* __restrict__ ns, const float* __restrict__ nd,
                                const float* __restrict__ tpc, const float* __restrict__ trc,
                                const float* __restrict__ tpf, const float* __restrict__ W0,
                                const float* __restrict__ num, const int* __restrict__ src,
                                const int* __restrict__ dst, const int* __restrict__ pc,
                                const int* __restrict__ rc, const int* __restrict__ pf,
                                float* __restrict__ y) {
    int e = (blockIdx.x * blockDim.x + threadIdx.x) >> 5;
    int lane = threadIdx.x & 31;
    if (e >= N_EDGES) return;
    size_t so = (size_t)src[e] * MLP_LD;
    size_t doff = (size_t)dst[e] * MLP_LD;
    int ipc = pc[e] * MLP_LD, irc = rc[e] * MLP_LD, ipf = pf[e] * MLP_LD;
    float n0 = num[(size_t)e * 5 + 0], n1 = num[(size_t)e * 5 + 1];
    float n2 = num[(size_t)e * 5 + 2], n3 = num[(size_t)e * 5 + 3];
    float n4 = num[(size_t)e * 5 + 4];
    const float* Wn = W0 + 280 * MLP_LD;
    #pragma unroll
    for (int t = 0; t < 10; t++) {
        int c = t * 32 + lane;
        float val = ns[so + c] + nd[doff + c] + tpc[ipc + c] + trc[irc + c] + tpf[ipf + c];
        val = fmaf(n0, Wn[c], val);
        val = fmaf(n1, Wn[MLP_LD + c], val);
        val = fmaf(n2, Wn[2 * MLP_LD + c], val);
        val = fmaf(n3, Wn[3 * MLP_LD + c], val);
        val = fmaf(n4, Wn[4 * MLP_LD + c], val);
        y[(size_t)e * MLP_LD + c] = fmaxf(val, 0.f);
    }
}

// ---------------- out init: fill with output bias ----------------
__global__ void out_init_kernel(float* __restrict__ out, const float* __restrict__ bo) {
    int idx = blockIdx.x * blockDim.x + threadIdx.x;
    if (idx < N_EDGES * 2) out[idx] = bo[idx & 1];
}

// ---------------- host ----------------
static inline int G(long long n) { return (int)((n + 255) / 256); }

extern "C" void kernel_launch(void* const* d_in, const int* in_sizes, int n_in,
                              void* d_out, int out_size) {
    const float* node_feats = (const float*)d_in[0];
    const float* numericals = (const float*)d_in[1];
    const float* W_emb = (const float*)d_in[2];
    const float* b_emb = (const float*)d_in[3];
    const float* WQ = (const float*)d_in[4];
    const float* bQ = (const float*)d_in[5];
    const float* WK = (const float*)d_in[6];
    const float* bK = (const float*)d_in[7];
    const float* WV = (const float*)d_in[8];
    const float* bV = (const float*)d_in[9];
    const float* WO = (const float*)d_in[10];
    const float* bO = (const float*)d_in[11];
    const float* ln1_g = (const float*)d_in[12];
    const float* ln1_b = (const float*)d_in[13];
    const float* ln2_g = (const float*)d_in[14];
    const float* ln2_b = (const float*)d_in[15];
    const float* W1 = (const float*)d_in[16];
    const float* b1 = (const float*)d_in[17];
    const float* W2 = (const float*)d_in[18];
    const float* b2 = (const float*)d_in[19];
    const float* curr_emb = (const float*)d_in[20];
    const float* pay_emb = (const float*)d_in[21];
    const float* mlp_Wh = (const float*)d_in[22];
    const float* mlp_bh = (const float*)d_in[23];
    const float* mlp_Wo = (const float*)d_in[24];
    const float* mlp_bo = (const float*)d_in[25];
    const int* src = (const int*)d_in[26];
    const int* dst = (const int*)d_in[27];
    const int* pc = (const int*)d_in[28];
    const int* rc = (const int*)d_in[29];
    const int* pf = (const int*)d_in[30];
    float* out = (float*)d_out;

    float *h, *x, *qkv, *attn, *tmp, *y0, *y1, *Wpad, *bpad, *Wopad;
    float *Wqkv, *bqkv, *ns, *nd, *tpc, *trc, *tpf, *zero;
    int *deg, *rowptr, *cursor, *srcs;
    unsigned *Wqkvh, *Wqkvl, *WOh, *WOl, *W1h, *W1l, *W2h, *W2l, *Wnsh, *Wnsl;
    cudaGetSymbolAddress((void**)&h, g_h);
    cudaGetSymbolAddress((void**)&x, g_x);
    cudaGetSymbolAddress((void**)&qkv, g_qkv);
    cudaGetSymbolAddress((void**)&attn, g_attn);
    cudaGetSymbolAddress((void**)&tmp, g_tmp);
    cudaGetSymbolAddress((void**)&y0, g_y0);
    cudaGetSymbolAddress((void**)&y1, g_y1);
    cudaGetSymbolAddress((void**)&Wpad, g_Wpad);
    cudaGetSymbolAddress((void**)&bpad, g_bpad);
    cudaGetSymbolAddress((void**)&Wopad, g_Wopad);
    cudaGetSymbolAddress((void**)&Wqkv, g_Wqkv);
    cudaGetSymbolAddress((void**)&bqkv, g_bqkv);
    cudaGetSymbolAddress((void**)&ns, g_ns);
    cudaGetSymbolAddress((void**)&nd, g_nd);
    cudaGetSymbolAddress((void**)&tpc, g_tpc);
    cudaGetSymbolAddress((void**)&trc, g_trc);
    cudaGetSymbolAddress((void**)&tpf, g_tpf);
    cudaGetSymbolAddress((void**)&zero, g_zero);
    cudaGetSymbolAddress((void**)&deg, g_deg);
    cudaGetSymbolAddress((void**)&rowptr, g_rowptr);
    cudaGetSymbolAddress((void**)&cursor, g_cursor);
    cudaGetSymbolAddress((void**)&srcs, g_srcs);
    cudaGetSymbolAddress((void**)&Wqkvh, g_Wqkv_h);
    cudaGetSymbolAddress((void**)&Wqkvl, g_Wqkv_l);
    cudaGetSymbolAddress((void**)&WOh, g_WO_h);
    cudaGetSymbolAddress((void**)&WOl, g_WO_l);
    cudaGetSymbolAddress((void**)&W1h, g_W1_h);
    cudaGetSymbolAddress((void**)&W1l, g_W1_l);
    cudaGetSymbolAddress((void**)&W2h, g_W2_h);
    cudaGetSymbolAddress((void**)&W2l, g_W2_l);
    cudaGetSymbolAddress((void**)&Wnsh, g_Wns_h);
    cudaGetSymbolAddress((void**)&Wnsl, g_Wns_l);

    // ---- one-time prep ----
    padW_kernel<<<G(3 * MLP_K * MLP_LD), 256>>>(mlp_Wh, Wpad);
    padb_kernel<<<G(3 * MLP_LD), 256>>>(mlp_bh, bpad, mlp_Wo, Wopad, zero);
    packqkv_kernel<<<G((long long)LAYERS * HID * 384), 256>>>(WQ, WK, WV, bQ, bK, bV,
                                                              Wqkv, bqkv);
    tables_kernel<<<G(37 * MLP_LD), 256>>>(curr_emb, pay_emb, Wpad, tpc, trc, tpf);

    // pack node weights to bf16 hi/lo words
    packw_kernel<<<G((long long)LAYERS * 64 * 384), 256>>>(Wqkv, Wqkvh, Wqkvl,
                                                           LAYERS, 384, 384);
    packw_kernel<<<G((long long)LAYERS * 64 * 128), 256>>>(WO, WOh, WOl,
                                                           LAYERS, 128, 128);
    packw_kernel<<<G((long long)LAYERS * 64 * 128), 256>>>(W1, W1h, W1l,
                                                           LAYERS, 128, 128);
    packw_kernel<<<G((long long)LAYERS * 64 * 128), 256>>>(W2, W2h, W2l,
                                                           LAYERS, 128, 128);
    packw_kernel<<<G((long long)2 * 64 * 384), 256>>>(Wpad, Wnsh, Wnsl,
                                                      2, 320, 384);

    // CSR build
    deg_zero_kernel<<<G(N_NODES), 256>>>(deg);
    deg_count_kernel<<<G(N_EDGES), 256>>>(dst, deg);
    scan_kernel<<<1, 1024>>>(deg, rowptr, cursor);
    scatter_kernel<<<G(N_EDGES), 256>>>(src, dst, cursor, srcs);

    embed_kernel<<<G((long long)N_NODES * HID), 256>>>(node_feats, W_emb, b_emb, h);

    // node-pipeline GEMMs: 3xBF16-split tensor cores
    auto bgemm = [&](const float* A, const unsigned* Wh_, const unsigned* Wl_, int ldw,
                     const float* bias, const float* res, float* C, int M, int N,
                     int relu) {
        dim3 grid((N + 127) / 128, (M + 127) / 128);
        bf16_gemm_kernel<<<grid, 256>>>(A, Wh_, Wl_, ldw, bias, res, C, M, N, relu);
    };

    for (int l = 0; l < LAYERS; l++) {
        const int BOFF = l * HID;
        ln_kernel<<<G((long long)N_NODES * 32), 256>>>(h, ln1_g + BOFF, ln1_b + BOFF, x);
        bgemm(x, Wqkvh + (size_t)l * 64 * 384, Wqkvl + (size_t)l * 64 * 384, 384,
              bqkv + l * 384, nullptr, qkv, N_NODES, 384, 0);
        attn_kernel<<<G((long long)N_NODES * 32), 256>>>(qkv, rowptr, srcs, attn);
        bgemm(attn, WOh + (size_t)l * 64 * 128, WOl + (size_t)l * 64 * 128, 128,
              bO + BOFF, h, h, N_NODES, 128, 0);
        ln_kernel<<<G((long long)N_NODES * 32), 256>>>(h, ln2_g + BOFF, ln2_b + BOFF, x);
        bgemm(x, W1h + (size_t)l * 64 * 128, W1l + (size_t)l * 64 * 128, 128,
              b1 + BOFF, nullptr, tmp, N_NODES, 128, 1);
        bgemm(tmp, W2h + (size_t)l * 64 * 128, W2l + (size_t)l * 64 * 128, 128,
              b2 + BOFF, h, h, N_NODES, 128, 0);
    }

    // ---- edge classifier ----
    bgemm(h, Wnsh, Wnsl, 384, bpad, nullptr, ns, N_NODES, 320, 0);
    bgemm(h, Wnsh + 64 * 384, Wnsl + 64 * 384, 384, zero, nullptr, nd,
          N_NODES, 320, 0);
    assemble_kernel<<<G((long long)N_EDGES * 32), 256>>>(
        ns, nd, tpc, trc, tpf, Wpad, numericals, src, dst, pc, rc, pf, y0);

    // layers 2,3: single-pass tf32 GEMMs; layer 3 fused with output projection
    out_init_kernel<<<G((long long)N_EDGES * 2), 256>>>(out, mlp_bo);
    int mblocks = (N_EDGES + 127) / 128;
    mlp_gemm_kernel<<<mblocks, 512>>>(
        y0, Wpad + 1 * MLP_K * MLP_LD, bpad + 1 * MLP_LD, y1, N_EDGES, nullptr, nullptr);
    mlp_gemm_kernel<<<mblocks, 512>>>(
        y1, Wpad + 2 * MLP_K * MLP_LD, bpad + 2 * MLP_LD, nullptr, N_EDGES, Wopad, out);
}